// round 12
// baseline (speedup 1.0000x reference)
#include <cuda_runtime.h>
#include <math.h>
#include <cstdint>

#define NH    12
#define NTOK  2048
#define BATCH 4
#define CDIM  768
#define HD    64
#define KEEP  1024
#define ROWS  (BATCH*NTOK)   /* 8192 */
#define C3    (3*CDIM)       /* 2304 */
#define NBH   (BATCH*NH)     /* 48 */
#define CLIPV 72.134689f     /* 50 * log2(e) */

// ---- scratch (static device globals; no runtime allocation) ----
__device__ float g_q[(size_t)ROWS * CDIM];          // q only, [row][768]
__device__ int   g_keep[NBH * KEEP];
__device__ float g_ksel [(size_t)NBH * KEEP * HD];  // [bh][j][d] row-major, tf32
__device__ float g_vselT[(size_t)NBH * HD * KEEP];  // [bh][d][slot] transposed+permuted
__device__ float g_attnout[(size_t)ROWS * CDIM];
__device__ float g_xhi[(size_t)ROWS * CDIM];
__device__ float g_xlo[(size_t)ROWS * CDIM];
__device__ float g_wqT_hi[(size_t)C3 * CDIM];       // w_qkv^T [2304][768]
__device__ float g_wqT_lo[(size_t)C3 * CDIM];
__device__ float g_wpT_hi[(size_t)CDIM * CDIM];
__device__ float g_wpT_lo[(size_t)CDIM * CDIM];

__device__ __forceinline__ float tf32_rna(float a) {
    float r; asm("cvt.rna.tf32.f32 %0, %1;" : "=f"(r) : "f"(a)); return r;
}
__device__ __forceinline__ float pexp(float s) {
    s = fminf(fmaxf(s, -CLIPV), CLIPV);
    float r; asm("ex2.approx.ftz.f32 %0, %1;" : "=f"(r) : "f"(s)); return r;
}
__device__ __forceinline__ uint32_t smem_u32(const void* p) {
    uint32_t a;
    asm("{ .reg .u64 t; cvta.to.shared.u64 t, %1; cvt.u32.u64 %0, t; }" : "=r"(a) : "l"(p));
    return a;
}
__device__ __forceinline__ void cp16(uint32_t dst, const float* src) {
    size_t ga = __cvta_generic_to_global(src);
    asm volatile("cp.async.cg.shared.global [%0], [%1], 16;" :: "r"(dst), "l"(ga));
}
__device__ __forceinline__ void mma_tf32(float& c0, float& c1, float& c2, float& c3,
                                         uint32_t a0, uint32_t a1, uint32_t a2, uint32_t a3,
                                         uint32_t b0, uint32_t b1) {
    asm volatile("mma.sync.aligned.m16n8k8.row.col.f32.tf32.tf32.f32 "
        "{%0,%1,%2,%3}, {%4,%5,%6,%7}, {%8,%9}, {%0,%1,%2,%3};"
        : "+f"(c0), "+f"(c1), "+f"(c2), "+f"(c3)
        : "r"(a0), "r"(a1), "r"(a2), "r"(a3), "r"(b0), "r"(b1));
}
#define LDSM4(r0_, r1_, r2_, r3_, addr_) \
    asm volatile("ldmatrix.sync.aligned.m8n8.x4.shared.b16 {%0,%1,%2,%3}, [%4];" \
        : "=r"(r0_), "=r"(r1_), "=r"(r2_), "=r"(r3_) : "r"(addr_))

// ============================================================================
// 3-stage cp.async mma.sync tf32 GEMM body (dense), ldmatrix feeds.
// C[M,N] = A[M,K] @ BT[N,K]^T, CTA tile 128x128, 8 warps (2m x 4n).
// TERMS=3: Ah*Bh + Ah*Bl + Al*Bh;  TERMS=2: Ah*(Bh+Bl).
// ============================================================================
template<int TERMS, int CH>
__device__ __forceinline__ void gemm_body(
    const float* __restrict__ Ahi, const float* __restrict__ Alo,
    const float* __restrict__ Bhi, const float* __restrict__ Blo,
    float* __restrict__ C, int K, int ldc,
    const float* __restrict__ bias, int do_clip, float* sm)
{
    constexpr int STAGES = 3;
    constexpr int T  = 128 * CH;
    constexpr int NT = (TERMS == 3) ? 4 : (TERMS + 1);
    constexpr int SS = NT * T;
    constexpr int GPR = CH / 4;
    constexpr int GPT = 128 * GPR / 256;

    const int tid = threadIdx.x, lane = tid & 31, wid = tid >> 5;
    const int g = lane >> 2, ct = lane & 3;
    const int wm = wid & 1, wn = wid >> 1;
    const int m0 = blockIdx.y * 128, n0 = blockIdx.x * 128;

    const int ao = ((lane >> 3) & 1) * 8 + (lane & 7);
    const int ak = lane >> 4;
    const int bo = (lane >> 4) * 8 + (lane & 7);
    const int bk = (lane >> 3) & 1;
    const int swzA = (CH == 16) ? ((ao >> 1) & 3) : (ao & 7);
    const int swzB = (CH == 16) ? ((bo >> 1) & 3) : (bo & 7);

    float acc[4][4][4];
#pragma unroll
    for (int mt = 0; mt < 4; mt++)
#pragma unroll
        for (int nt = 0; nt < 4; nt++)
#pragma unroll
            for (int i = 0; i < 4; i++) acc[mt][nt][i] = 0.f;

    const uint32_t smb = smem_u32(sm);
    const int NC = K / CH;

    auto issue = [&](int c) {
        const uint32_t sb = smb + (uint32_t)((c % STAGES) * SS * 4);
        const int k0 = c * CH;
#pragma unroll
        for (int j = 0; j < GPT; j++) {
            int gidx = tid + j * 256;
            int row = gidx / GPR, gg = gidx & (GPR - 1);
            int swz = (CH == 16) ? ((row >> 1) & 3) : (row & 7);
            uint32_t off = (uint32_t)((row * CH + ((gg ^ swz) << 2)) * 4);
            int gk = k0 + gg * 4;
            cp16(sb + off,                   Ahi + (size_t)(m0 + row) * K + gk);
            cp16(sb + (uint32_t)T * 4 + off, Bhi + (size_t)(n0 + row) * K + gk);
            if (TERMS >= 2)
                cp16(sb + 2u * T * 4 + off, Blo + (size_t)(n0 + row) * K + gk);
            if (TERMS == 3)
                cp16(sb + 3u * T * 4 + off, Alo + (size_t)(m0 + row) * K + gk);
        }
        asm volatile("cp.async.commit_group;" ::: "memory");
    };

    issue(0);
    issue(1);

    for (int c = 0; c < NC; c++) {
        asm volatile("cp.async.wait_group %0;" :: "n"(STAGES - 2));
        __syncthreads();
        if (c + STAGES - 1 < NC) issue(c + STAGES - 1);

        const uint32_t stb = smb + (uint32_t)((c % STAGES) * SS * 4);
        uint32_t aAh[4], aAl[4], aBh[2], aBl[2];
#pragma unroll
        for (int mt = 0; mt < 4; mt++) {
            int row = wm * 64 + mt * 16 + ao;
            aAh[mt] = stb + (uint32_t)(row * CH * 4);
            if (TERMS == 3) aAl[mt] = aAh[mt] + 3u * T * 4;
        }
#pragma unroll
        for (int ntp = 0; ntp < 2; ntp++) {
            int row = wn * 32 + ntp * 16 + bo;
            aBh[ntp] = stb + (uint32_t)(T * 4 + row * CH * 4);
            if (TERMS >= 2) aBl[ntp] = aBh[ntp] + (uint32_t)(T * 4);
        }

#pragma unroll
        for (int ks = 0; ks < CH / 8; ks++) {
            const uint32_t offA = (uint32_t)(((2 * ks + ak) ^ swzA) << 4);
            const uint32_t offB = (uint32_t)(((2 * ks + bk) ^ swzB) << 4);
            uint32_t afh[4][4], afl[4][4], bfh[4][2], bfl[4][2];
#pragma unroll
            for (int mt = 0; mt < 4; mt++) {
                LDSM4(afh[mt][0], afh[mt][1], afh[mt][2], afh[mt][3], aAh[mt] + offA);
                if (TERMS == 3)
                    LDSM4(afl[mt][0], afl[mt][1], afl[mt][2], afl[mt][3], aAl[mt] + offA);
            }
            LDSM4(bfh[0][0], bfh[0][1], bfh[1][0], bfh[1][1], aBh[0] + offB);
            LDSM4(bfh[2][0], bfh[2][1], bfh[3][0], bfh[3][1], aBh[1] + offB);
            if (TERMS >= 2) {
                LDSM4(bfl[0][0], bfl[0][1], bfl[1][0], bfl[1][1], aBl[0] + offB);
                LDSM4(bfl[2][0], bfl[2][1], bfl[3][0], bfl[3][1], aBl[1] + offB);
            }
#pragma unroll
            for (int mt = 0; mt < 4; mt++)
#pragma unroll
                for (int nt = 0; nt < 4; nt++) {
                    float* a = acc[mt][nt];
                    mma_tf32(a[0], a[1], a[2], a[3],
                             afh[mt][0], afh[mt][1], afh[mt][2], afh[mt][3],
                             bfh[nt][0], bfh[nt][1]);
                    if (TERMS >= 2)
                        mma_tf32(a[0], a[1], a[2], a[3],
                                 afh[mt][0], afh[mt][1], afh[mt][2], afh[mt][3],
                                 bfl[nt][0], bfl[nt][1]);
                    if (TERMS == 3)
                        mma_tf32(a[0], a[1], a[2], a[3],
                                 afl[mt][0], afl[mt][1], afl[mt][2], afl[mt][3],
                                 bfh[nt][0], bfh[nt][1]);
                }
        }
    }

#pragma unroll
    for (int mt = 0; mt < 4; mt++) {
#pragma unroll
        for (int nt = 0; nt < 4; nt++) {
            int row = m0 + wm * 64 + mt * 16 + g;
            int col = n0 + wn * 32 + nt * 8 + ct * 2;
            float v0 = acc[mt][nt][0], v1 = acc[mt][nt][1];
            float v2 = acc[mt][nt][2], v3 = acc[mt][nt][3];
            if (bias) {
                float b0 = bias[col], b1 = bias[col + 1];
                v0 += b0; v1 += b1; v2 += b0; v3 += b1;
            }
            if (do_clip) {
                v0 = fminf(fmaxf(v0, -10.f), 10.f);
                v1 = fminf(fmaxf(v1, -10.f), 10.f);
                v2 = fminf(fmaxf(v2, -10.f), 10.f);
                v3 = fminf(fmaxf(v3, -10.f), 10.f);
            }
            float2 lo2; lo2.x = v0; lo2.y = v1;
            float2 hi2; hi2.x = v2; hi2.y = v3;
            *(float2*)(C + (size_t)row * ldc + col) = lo2;
            *(float2*)(C + (size_t)(row + 8) * ldc + col) = hi2;
        }
    }
}

// q only: [8192 x 768], 3-term tf32 (top-k safe)
__global__ __launch_bounds__(256, 2) void q_gemm(
    const float* __restrict__ xhi, const float* __restrict__ xlo,
    const float* __restrict__ wTh, const float* __restrict__ wTl,
    float* __restrict__ C)
{
    extern __shared__ float sm[];
    gemm_body<3, 16>(xhi, xlo, wTh, wTl, C, CDIM, CDIM, nullptr, 0, sm);
}

__global__ __launch_bounds__(256, 2) void proj_gemm(
    const float* __restrict__ A, const float* __restrict__ Bh,
    const float* __restrict__ Bl, const float* __restrict__ bias,
    float* __restrict__ C)
{
    extern __shared__ float sm[];
    gemm_body<2, 16>(A, nullptr, Bh, Bl, C, CDIM, CDIM, bias, 1, sm);
}

// ============================================================================
// Gather-GEMM: per (b,h) compute Ksel = x[keep]·w_k[h], Vsel = x[keep]·w_v[h].
// ============================================================================
__global__ __launch_bounds__(256, 2) void kvg_gemm(
    const float* __restrict__ xhi, const float* __restrict__ wTh,
    const int* __restrict__ keep,
    float* __restrict__ ksel, float* __restrict__ vselT)
{
    extern __shared__ float sm[];
    constexpr int CH = 32, STAGES = 3;
    constexpr int T  = 128 * CH;
    constexpr int SS = 2 * T;

    const int tid = threadIdx.x, lane = tid & 31, wid = tid >> 5;
    const int g = lane >> 2, ct = lane & 3;
    const int wm = wid & 1, wn = wid >> 1;
    const int m0 = blockIdx.x * 128;
    const int bh = blockIdx.y, b = bh / NH, h = bh % NH;

    const int ao = ((lane >> 3) & 1) * 8 + (lane & 7);
    const int ak = lane >> 4;
    const int bo = (lane >> 4) * 8 + (lane & 7);
    const int bk = (lane >> 3) & 1;
    const int swzA = ao & 7;
    const int swzB = bo & 7;

    const int lrow = tid >> 3, lgg = tid & 7;
    const float* aptr[4];
    const float* bptr[4];
    uint32_t soff[4];
#pragma unroll
    for (int j = 0; j < 4; j++) {
        int row = lrow + 32 * j;
        int tok = keep[bh * KEEP + m0 + row];
        aptr[j] = xhi + (size_t)(b * NTOK + tok) * CDIM + lgg * 4;
        int wrow = (row < 64) ? (CDIM + h * HD + row) : (2 * CDIM + h * HD + row - 64);
        bptr[j] = wTh + (size_t)wrow * CDIM + lgg * 4;
        soff[j] = (uint32_t)((row * CH + ((lgg ^ (row & 7)) << 2)) * 4);
    }

    float acc[4][4][4];
#pragma unroll
    for (int mt = 0; mt < 4; mt++)
#pragma unroll
        for (int nt = 0; nt < 4; nt++)
#pragma unroll
            for (int i = 0; i < 4; i++) acc[mt][nt][i] = 0.f;

    const uint32_t smb = smem_u32(sm);
    const int NC = CDIM / CH;

    auto issue = [&](int c) {
        const uint32_t sb = smb + (uint32_t)((c % STAGES) * SS * 4);
        const int k0 = c * CH;
#pragma unroll
        for (int j = 0; j < 4; j++) {
            cp16(sb + soff[j],                   aptr[j] + k0);
            cp16(sb + (uint32_t)T * 4 + soff[j], bptr[j] + k0);
        }
        asm volatile("cp.async.commit_group;" ::: "memory");
    };

    issue(0);
    issue(1);

    for (int c = 0; c < NC; c++) {
        asm volatile("cp.async.wait_group %0;" :: "n"(STAGES - 2));
        __syncthreads();
        if (c + STAGES - 1 < NC) issue(c + STAGES - 1);

        const uint32_t stb = smb + (uint32_t)((c % STAGES) * SS * 4);
        uint32_t aA[4], aB[2];
#pragma unroll
        for (int mt = 0; mt < 4; mt++)
            aA[mt] = stb + (uint32_t)((wm * 64 + mt * 16 + ao) * CH * 4);
#pragma unroll
        for (int ntp = 0; ntp < 2; ntp++)
            aB[ntp] = stb + (uint32_t)(T * 4 + (wn * 32 + ntp * 16 + bo) * CH * 4);

#pragma unroll
        for (int ks = 0; ks < CH / 8; ks++) {
            const uint32_t offA = (uint32_t)(((2 * ks + ak) ^ swzA) << 4);
            const uint32_t offB = (uint32_t)(((2 * ks + bk) ^ swzB) << 4);
            uint32_t af[4][4], bf[4][2];
#pragma unroll
            for (int mt = 0; mt < 4; mt++)
                LDSM4(af[mt][0], af[mt][1], af[mt][2], af[mt][3], aA[mt] + offA);
            LDSM4(bf[0][0], bf[0][1], bf[1][0], bf[1][1], aB[0] + offB);
            LDSM4(bf[2][0], bf[2][1], bf[3][0], bf[3][1], aB[1] + offB);
#pragma unroll
            for (int mt = 0; mt < 4; mt++)
#pragma unroll
                for (int nt = 0; nt < 4; nt++)
                    mma_tf32(acc[mt][nt][0], acc[mt][nt][1], acc[mt][nt][2], acc[mt][nt][3],
                             af[mt][0], af[mt][1], af[mt][2], af[mt][3],
                             bf[nt][0], bf[nt][1]);
        }
    }

    __syncthreads();

    if (wn < 2) {
#pragma unroll
        for (int mt = 0; mt < 4; mt++) {
#pragma unroll
            for (int nt = 0; nt < 4; nt++) {
                int j0 = wm * 64 + mt * 16 + g;
                int d  = wn * 32 + nt * 8 + ct * 2;
                float2 a;
                a.x = tf32_rna(acc[mt][nt][0]); a.y = tf32_rna(acc[mt][nt][1]);
                *(float2*)(ksel + ((size_t)bh * KEEP + m0 + j0) * HD + d) = a;
                float2 c2;
                c2.x = tf32_rna(acc[mt][nt][2]); c2.y = tf32_rna(acc[mt][nt][3]);
                *(float2*)(ksel + ((size_t)bh * KEEP + m0 + j0 + 8) * HD + d) = c2;
            }
        }
    } else {
        float* vst = sm;   // [64][132]
#pragma unroll
        for (int mt = 0; mt < 4; mt++) {
#pragma unroll
            for (int nt = 0; nt < 4; nt++) {
                int j0 = wm * 64 + mt * 16 + g;
                int j1 = j0 + 8;
                int d  = (wn - 2) * 32 + nt * 8 + ct * 2;
                int s0 = (j0 & ~7) | ((j0 & 1) << 2) | ((j0 & 7) >> 1);
                int s1 = (j1 & ~7) | ((j1 & 1) << 2) | ((j1 & 7) >> 1);
                vst[d * 132 + s0]       = tf32_rna(acc[mt][nt][0]);
                vst[(d + 1) * 132 + s0] = tf32_rna(acc[mt][nt][1]);
                vst[d * 132 + s1]       = tf32_rna(acc[mt][nt][2]);
                vst[(d + 1) * 132 + s1] = tf32_rna(acc[mt][nt][3]);
            }
        }
    }
    __syncthreads();

    for (int i = tid; i < 64 * 32; i += 256) {
        int d = i >> 5, f = (i & 31) * 4;
        float4 v;
        v.x = sm[d * 132 + f];     v.y = sm[d * 132 + f + 1];
        v.z = sm[d * 132 + f + 2]; v.w = sm[d * 132 + f + 3];
        *(float4*)(vselT + ((size_t)bh * HD + d) * KEEP + m0 + f) = v;
    }
}

// ============================================================================
// x -> (hi, lo) tf32 split
// ============================================================================
__global__ void xsplit_kernel(const float* __restrict__ x, float* __restrict__ hi,
                              float* __restrict__ lo, int n4)
{
    int i = blockIdx.x * blockDim.x + threadIdx.x;
    if (i >= n4) return;
    float4 v = ((const float4*)x)[i];
    float4 h, l;
    h.x = tf32_rna(v.x); l.x = tf32_rna(v.x - h.x);
    h.y = tf32_rna(v.y); l.y = tf32_rna(v.y - h.y);
    h.z = tf32_rna(v.z); l.z = tf32_rna(v.z - h.z);
    h.w = tf32_rna(v.w); l.w = tf32_rna(v.w - h.w);
    ((float4*)hi)[i] = h;
    ((float4*)lo)[i] = l;
}

// ============================================================================
// combined weight transpose + tf32 split: both w_qkv and w_proj in one launch
// ============================================================================
__global__ void wsplit_kernel(const float* __restrict__ in1, float* __restrict__ ohi1,
                              float* __restrict__ olo1,
                              const float* __restrict__ in2, float* __restrict__ ohi2,
                              float* __restrict__ olo2)
{
    __shared__ float t[32][33];
    const int K = CDIM;
    const float* in; float *ohi, *olo; int n0;
    if (blockIdx.x < C3 / 32) {
        in = in1; ohi = ohi1; olo = olo1; n0 = blockIdx.x * 32;
    } else {
        in = in2; ohi = ohi2; olo = olo2; n0 = (blockIdx.x - C3 / 32) * 32;
    }
    const int N = (blockIdx.x < C3 / 32) ? C3 : CDIM;
    const int k0 = blockIdx.y * 32;
    const int tx = threadIdx.x, ty = threadIdx.y;
#pragma unroll
    for (int i = 0; i < 4; i++)
        t[ty + i * 8][tx] = in[(size_t)(k0 + ty + i * 8) * N + n0 + tx];
    __syncthreads();
#pragma unroll
    for (int i = 0; i < 4; i++) {
        float v = t[tx][ty + i * 8];
        float h = tf32_rna(v);
        ohi[(size_t)(n0 + ty + i * 8) * K + k0 + tx] = h;
        olo[(size_t)(n0 + ty + i * 8) * K + k0 + tx] = tf32_rna(v - h);
    }
}

// ============================================================================
// Per-(b,h) top-KEEP: scores inline (sum_d q^2), bitonic sort (set semantics).
// ============================================================================
__global__ __launch_bounds__(1024) void topk_kernel(
    const float* __restrict__ q, int* __restrict__ keep)
{
    __shared__ unsigned long long keys[NTOK];
    const int bh = blockIdx.x, t = threadIdx.x;
    const int h = bh % NH, b = bh / NH;
    for (int i = t; i < NTOK; i += 1024) {
        const float4* qp = (const float4*)(q + (size_t)(b * NTOK + i) * CDIM + h * HD);
        float s = 0.f;
#pragma unroll
        for (int u = 0; u < 16; u++) {
            float4 v = qp[u];
            s += v.x * v.x + v.y * v.y + v.z * v.z + v.w * v.w;
        }
        keys[i] = ((unsigned long long)__float_as_uint(s) << 32) | (unsigned)(NTOK - 1 - i);
    }
    for (int k = 2; k <= NTOK; k <<= 1) {
        for (int j = k >> 1; j > 0; j >>= 1) {
            __syncthreads();
            for (int i = t; i < NTOK; i += 1024) {
                int ixj = i ^ j;
                if (ixj > i) {
                    unsigned long long a = keys[i], c = keys[ixj];
                    bool asc = ((i & k) == 0);
                    if ((a > c) == asc) { keys[i] = c; keys[ixj] = a; }
                }
            }
        }
    }
    __syncthreads();
    if (t < KEEP) {
        keep[bh * KEEP + t] = (NTOK - 1) - (int)(keys[NTOK - KEEP + t] & 0xffffffffu);
    }
}

// ============================================================================
// mma.sync attention, warp-row-split + 2-stage cp.async K/V pipeline.
// Key chunks of 32 -> smem 64KB -> 3 CTAs/SM (24 warps) for latency hiding.
// smem: Qs[128][64] (32K) | 2 stages x { K[32][64] 8K + V[64][32] 8K }.
// ============================================================================
__global__ __launch_bounds__(256, 3) void attn_mma(
    const float* __restrict__ q, const float* __restrict__ ksel,
    const float* __restrict__ vselT, float* __restrict__ out)
{
    extern __shared__ float sm[];
    float* Qs = sm;
    const uint32_t smb    = smem_u32(sm);
    const uint32_t stage0 = smb + 8192u * 4;   // stage s at stage0 + s*16KB

    const int tid = threadIdx.x, lane = tid & 31, wid = tid >> 5;
    const int g = lane >> 2, ct = lane & 3;
    const int bh = blockIdx.y, b = bh / NH, h = bh % NH;
    const int qbase = blockIdx.x * 128;

    const int ao = ((lane >> 3) & 1) * 8 + (lane & 7);
    const int ak = lane >> 4;
    const int bo = (lane >> 4) * 8 + (lane & 7);
    const int bk = (lane >> 3) & 1;
    const int swzq = ao & 7;
    const int swzb = bo & 7;

    {
        int j = tid & 127, half = tid >> 7;
        const float* qrow = q + (size_t)(b * NTOK + qbase + j) * CDIM + h * HD + half * 32;
        const float QSC = 0.125f * 1.44269504f;
#pragma unroll
        for (int i = 0; i < 8; i++) {
            float4 v = *(const float4*)(qrow + i * 4);
            v.x = tf32_rna(v.x * QSC); v.y = tf32_rna(v.y * QSC);
            v.z = tf32_rna(v.z * QSC); v.w = tf32_rna(v.w * QSC);
            int c = half * 32 + i * 4;
            *(float4*)&Qs[j * 64 + (c ^ ((j & 7) << 2))] = v;
        }
    }

    const float* kbase = ksel  + (size_t)bh * KEEP * HD;
    const float* vbase = vselT + (size_t)bh * HD * KEEP;

    // loader: K[32 rows][16 groups] (2/thread) + V[64 rows][8 groups] (2/thread)
    auto issue = [&](int kc) {
        const uint32_t sb = stage0 + (uint32_t)((kc & 1) * 4096 * 4);
#pragma unroll
        for (int j = 0; j < 2; j++) {
            int gidx = tid + j * 256;
            int row = gidx >> 4, gg = gidx & 15;
            uint32_t off = (uint32_t)((row * 64 + ((gg ^ (row & 7)) << 2)) * 4);
            cp16(sb + off, kbase + (size_t)(kc * 32 + row) * HD + gg * 4);
            int vrow = gidx >> 3, vgg = gidx & 7;
            vrow &= 63;
            if (j == 1) vrow = (gidx - 256) >> 3 | 32;   // rows 32..63
            // simpler: recompute below
        }
        // K: 512 groups, V: 512 groups; do each in its own loop for clarity
        asm volatile("" ::: "memory");
#pragma unroll
        for (int j = 0; j < 2; j++) {
            int gidx = tid + j * 256;
            int vrow = gidx >> 3, vgg = gidx & 7;
            uint32_t off = (uint32_t)((vrow * 32 + ((vgg ^ (vrow & 7)) << 2)) * 4);
            cp16(sb + 2048u * 4 + off, vbase + (size_t)vrow * KEEP + kc * 32 + vgg * 4);
        }
        asm volatile("cp.async.commit_group;" ::: "memory");
    };

    const uint32_t qa_base = smb + (uint32_t)((wid * 16 + ao) * 64 * 4);

    float P[4][4];
    float O[8][4];
    float lp0 = 0.f, lp1 = 0.f;
#pragma unroll
    for (int dt = 0; dt < 8; dt++)
#pragma unroll
        for (int i = 0; i < 4; i++) O[dt][i] = 0.f;

    issue(0);

    for (int kc = 0; kc < KEEP / 32; kc++) {
        if (kc + 1 < KEEP / 32) {
            issue(kc + 1);
            asm volatile("cp.async.wait_group 1;" ::: "memory");
        } else {
            asm volatile("cp.async.wait_group 0;" ::: "memory");
        }
        __syncthreads();

        const uint32_t kst = stage0 + (uint32_t)((kc & 1) * 4096 * 4);
        const uint32_t vst = kst + 2048u * 4;

        // ---- S = (Q*scale) @ K^T : 16 rows x 32 keys
#pragma unroll
        for (int nt = 0; nt < 4; nt++)
#pragma unroll
            for (int i = 0; i < 4; i++) P[nt][i] = 0.f;

#pragma unroll
        for (int ks = 0; ks < 8; ks++) {
            const uint32_t offq = (uint32_t)(((2 * ks + ak) ^ swzq) << 4);
            const uint32_t offb = (uint32_t)(((2 * ks + bk) ^ swzb) << 4);
            uint32_t qa0, qa1, qa2, qa3;
            LDSM4(qa0, qa1, qa2, qa3, qa_base + offq);
#pragma unroll
            for (int ntp = 0; ntp < 2; ntp++) {
                uint32_t k00, k01, k10, k11;
                LDSM4(k00, k01, k10, k11, kst + (uint32_t)((ntp * 16 + bo) * 64 * 4) + offb);
                mma_tf32(P[2 * ntp][0], P[2 * ntp][1], P[2 * ntp][2], P[2 * ntp][3],
                         qa0, qa1, qa2, qa3, k00, k01);
                mma_tf32(P[2 * ntp + 1][0], P[2 * ntp + 1][1], P[2 * ntp + 1][2], P[2 * ntp + 1][3],
                         qa0, qa1, qa2, qa3, k10, k11);
            }
        }

        // ---- p = exp2(clip(s)); accumulate row sums
#pragma unroll
        for (int nt = 0; nt < 4; nt++) {
            float p0 = pexp(P[nt][0]);
            float p1 = pexp(P[nt][1]);
            float p2 = pexp(P[nt][2]);
            float p3 = pexp(P[nt][3]);
            lp0 += p0 + p1;
            lp1 += p2 + p3;
            P[nt][0] = p0; P[nt][1] = p1; P[nt][2] = p2; P[nt][3] = p3;
        }

        // ---- O += P @ V  (P registers as A; V slot-permuted, rows=d, 32 slots)
#pragma unroll
        for (int ks = 0; ks < 4; ks++) {
            const uint32_t offv = (uint32_t)(((2 * ks + bk) ^ swzb) << 4);
            uint32_t a0 = __float_as_uint(P[ks][0]);
            uint32_t a1 = __float_as_uint(P[ks][2]);
            uint32_t a2 = __float_as_uint(P[ks][1]);
            uint32_t a3 = __float_as_uint(P[ks][3]);
#pragma unroll
            for (int dtp = 0; dtp < 4; dtp++) {
                uint32_t v00, v01, v10, v11;
                LDSM4(v00, v01, v10, v11, vst + (uint32_t)((dtp * 16 + bo) * 32 * 4) + offv);
                mma_tf32(O[2 * dtp][0], O[2 * dtp][1], O[2 * dtp][2], O[2 * dtp][3],
                         a0, a1, a2, a3, v00, v01);
                mma_tf32(O[2 * dtp + 1][0], O[2 * dtp + 1][1], O[2 * dtp + 1][2], O[2 * dtp + 1][3],
                         a0, a1, a2, a3, v10, v11);
            }
        }
        __syncthreads();
    }

    lp0 += __shfl_xor_sync(0xffffffffu, lp0, 1);
    lp0 += __shfl_xor_sync(0xffffffffu, lp0, 2);
    lp1 += __shfl_xor_sync(0xffffffffu, lp1, 1);
    lp1 += __shfl_xor_sync(0xffffffffu, lp1, 2);
    const float li0 = 1.f / lp0, li1 = 1.f / lp1;

    const int row0 = qbase + wid * 16 + g;
#pragma unroll
    for (int dt = 0; dt < 8; dt++) {
        int d0 = dt * 8 + 2 * ct;
        float2 a;
        a.x = tf32_rna(O[dt][0] * li0);
        a.y = tf32_rna(O[dt][1] * li0);
        *(float2*)&out[(size_t)(b * NTOK + row0) * CDIM + h * HD + d0] = a;
        float2 c;
        c.x = tf32_rna(O[dt][2] * li1);
        c.y = tf32_rna(O[dt][3] * li1);
        *(float2*)&out[(size_t)(b * NTOK + row0 + 8) * CDIM + h * HD + d0] = c;
    }
}

// ============================================================================
// launch
// ============================================================================
extern "C" void kernel_launch(void* const* d_in, const int* in_sizes, int n_in,
                              void* d_out, int out_size)
{
    (void)in_sizes; (void)n_in; (void)out_size;
    const float* x      = (const float*)d_in[0];
    const float* w_qkv  = (const float*)d_in[1];
    const float* w_proj = (const float*)d_in[2];
    const float* b_proj = (const float*)d_in[3];
    float* out = (float*)d_out;

    float *q_p, *ks_p, *vT_p, *ao_p, *xhi_p, *xlo_p;
    float *wqh_p, *wql_p, *wph_p, *wpl_p;
    int* keep_p;
    cudaGetSymbolAddress((void**)&q_p,    g_q);
    cudaGetSymbolAddress((void**)&keep_p, g_keep);
    cudaGetSymbolAddress((void**)&ks_p,   g_ksel);
    cudaGetSymbolAddress((void**)&vT_p,   g_vselT);
    cudaGetSymbolAddress((void**)&ao_p,   g_attnout);
    cudaGetSymbolAddress((void**)&xhi_p,  g_xhi);
    cudaGetSymbolAddress((void**)&xlo_p,  g_xlo);
    cudaGetSymbolAddress((void**)&wqh_p,  g_wqT_hi);
    cudaGetSymbolAddress((void**)&wql_p,  g_wqT_lo);
    cudaGetSymbolAddress((void**)&wph_p,  g_wpT_hi);
    cudaGetSymbolAddress((void**)&wpl_p,  g_wpT_lo);

    const int smem_q    = 3 * 8192 * (int)sizeof(float);   // 98304
    const int smem_proj = 3 * 6144 * (int)sizeof(float);   // 73728
    const int smem_kvg  = 3 * 8192 * (int)sizeof(float);   // 98304
    cudaFuncSetAttribute(q_gemm,    cudaFuncAttributeMaxDynamicSharedMemorySize, smem_q);
    cudaFuncSetAttribute(proj_gemm, cudaFuncAttributeMaxDynamicSharedMemorySize, smem_proj);
    cudaFuncSetAttribute(kvg_gemm,  cudaFuncAttributeMaxDynamicSharedMemorySize, smem_kvg);
    const int attn_smem = (8192 + 2 * 4096) * (int)sizeof(float);   // 65536
    cudaFuncSetAttribute(attn_mma, cudaFuncAttributeMaxDynamicSharedMemorySize, attn_smem);

    // 0) tf32 splits (weights merged into one launch)
    xsplit_kernel<<<(ROWS * CDIM / 4 + 255) / 256, 256>>>(x, xhi_p, xlo_p, ROWS * CDIM / 4);
    wsplit_kernel<<<dim3(C3 / 32 + CDIM / 32, CDIM / 32), dim3(32, 8)>>>(
        w_qkv, wqh_p, wql_p, w_proj, wph_p, wpl_p);

    // 1) q = x @ w_q  (3-term tf32)
    q_gemm<<<dim3(CDIM / 128, ROWS / 128), 256, smem_q>>>(
        xhi_p, xlo_p, wqh_p, wql_p, q_p);

    // 2) top-k (scores fused)
    topk_kernel<<<NBH, 1024>>>(q_p, keep_p);

    // 3) gather-GEMM: Ksel / Vsel^T for selected tokens only
    kvg_gemm<<<dim3(KEEP / 128, NBH), 256, smem_kvg>>>(
        xhi_p, wqh_p, keep_p, ks_p, vT_p);

    // 4) attention on tensor cores (chunk 32, 3 CTAs/SM)
    attn_mma<<<dim3(NTOK / 128, NBH), 256, attn_smem>>>(q_p, ks_p, vT_p, ao_p);

    // 5) out = clip(attnout @ w_proj + b_proj, -10, 10)
    proj_gemm<<<dim3(CDIM / 128, ROWS / 128), 256, smem_proj>>>(
        ao_p, wph_p, wpl_p, b_proj, out);
}

// round 13
// speedup vs baseline: 1.0424x; 1.0424x over previous
#include <cuda_runtime.h>
#include <math.h>
#include <cstdint>

#define NH    12
#define NTOK  2048
#define BATCH 4
#define CDIM  768
#define HD    64
#define KEEP  1024
#define ROWS  (BATCH*NTOK)   /* 8192 */
#define C3    (3*CDIM)       /* 2304 */
#define NBH   (BATCH*NH)     /* 48 */
#define CLIPV 72.134689f     /* 50 * log2(e) */

// ---- scratch (static device globals; no runtime allocation) ----
__device__ float g_q[(size_t)ROWS * CDIM];          // q only, [row][768]
__device__ float g_scores[NBH * NTOK];
__device__ int   g_keep[NBH * KEEP];
__device__ float g_ksel [(size_t)NBH * KEEP * HD];  // [bh][j][d] row-major, tf32
__device__ float g_vselT[(size_t)NBH * HD * KEEP];  // [bh][d][slot] transposed+permuted
__device__ float g_attnout[(size_t)ROWS * CDIM];
__device__ float g_xhi[(size_t)ROWS * CDIM];
__device__ float g_xlo[(size_t)ROWS * CDIM];
__device__ float g_wqT_hi[(size_t)C3 * CDIM];       // w_qkv^T [2304][768]
__device__ float g_wqT_lo[(size_t)C3 * CDIM];
__device__ float g_wpT_hi[(size_t)CDIM * CDIM];
__device__ float g_wpT_lo[(size_t)CDIM * CDIM];

__device__ __forceinline__ float tf32_rna(float a) {
    float r; asm("cvt.rna.tf32.f32 %0, %1;" : "=f"(r) : "f"(a)); return r;
}
__device__ __forceinline__ float pexp(float s) {
    s = fminf(fmaxf(s, -CLIPV), CLIPV);
    float r; asm("ex2.approx.ftz.f32 %0, %1;" : "=f"(r) : "f"(s)); return r;
}
__device__ __forceinline__ uint32_t smem_u32(const void* p) {
    uint32_t a;
    asm("{ .reg .u64 t; cvta.to.shared.u64 t, %1; cvt.u32.u64 %0, t; }" : "=r"(a) : "l"(p));
    return a;
}
__device__ __forceinline__ void cp16(uint32_t dst, const float* src) {
    size_t ga = __cvta_generic_to_global(src);
    asm volatile("cp.async.cg.shared.global [%0], [%1], 16;" :: "r"(dst), "l"(ga));
}
__device__ __forceinline__ void mma_tf32(float& c0, float& c1, float& c2, float& c3,
                                         uint32_t a0, uint32_t a1, uint32_t a2, uint32_t a3,
                                         uint32_t b0, uint32_t b1) {
    asm volatile("mma.sync.aligned.m16n8k8.row.col.f32.tf32.tf32.f32 "
        "{%0,%1,%2,%3}, {%4,%5,%6,%7}, {%8,%9}, {%0,%1,%2,%3};"
        : "+f"(c0), "+f"(c1), "+f"(c2), "+f"(c3)
        : "r"(a0), "r"(a1), "r"(a2), "r"(a3), "r"(b0), "r"(b1));
}
#define LDSM4(r0_, r1_, r2_, r3_, addr_) \
    asm volatile("ldmatrix.sync.aligned.m8n8.x4.shared.b16 {%0,%1,%2,%3}, [%4];" \
        : "=r"(r0_), "=r"(r1_), "=r"(r2_), "=r"(r3_) : "r"(addr_))

// ============================================================================
// 3-stage cp.async mma.sync tf32 GEMM body (dense), ldmatrix feeds.
// C[M,N] = A[M,K] @ BT[N,K]^T, CTA tile 128x128, 8 warps (2m x 4n).
// TERMS=3: Ah*Bh + Ah*Bl + Al*Bh;  TERMS=2: Ah*(Bh+Bl).
// ============================================================================
template<int TERMS, int CH>
__device__ __forceinline__ void gemm_body(
    const float* __restrict__ Ahi, const float* __restrict__ Alo,
    const float* __restrict__ Bhi, const float* __restrict__ Blo,
    float* __restrict__ C, int K, int ldc,
    const float* __restrict__ bias, int do_clip, float* sm)
{
    constexpr int STAGES = 3;
    constexpr int T  = 128 * CH;
    constexpr int NT = (TERMS == 3) ? 4 : (TERMS + 1);
    constexpr int SS = NT * T;
    constexpr int GPR = CH / 4;
    constexpr int GPT = 128 * GPR / 256;

    const int tid = threadIdx.x, lane = tid & 31, wid = tid >> 5;
    const int g = lane >> 2, ct = lane & 3;
    const int wm = wid & 1, wn = wid >> 1;
    const int m0 = blockIdx.y * 128, n0 = blockIdx.x * 128;

    const int ao = ((lane >> 3) & 1) * 8 + (lane & 7);
    const int ak = lane >> 4;
    const int bo = (lane >> 4) * 8 + (lane & 7);
    const int bk = (lane >> 3) & 1;
    const int swzA = (CH == 16) ? ((ao >> 1) & 3) : (ao & 7);
    const int swzB = (CH == 16) ? ((bo >> 1) & 3) : (bo & 7);

    float acc[4][4][4];
#pragma unroll
    for (int mt = 0; mt < 4; mt++)
#pragma unroll
        for (int nt = 0; nt < 4; nt++)
#pragma unroll
            for (int i = 0; i < 4; i++) acc[mt][nt][i] = 0.f;

    const uint32_t smb = smem_u32(sm);
    const int NC = K / CH;

    auto issue = [&](int c) {
        const uint32_t sb = smb + (uint32_t)((c % STAGES) * SS * 4);
        const int k0 = c * CH;
#pragma unroll
        for (int j = 0; j < GPT; j++) {
            int gidx = tid + j * 256;
            int row = gidx / GPR, gg = gidx & (GPR - 1);
            int swz = (CH == 16) ? ((row >> 1) & 3) : (row & 7);
            uint32_t off = (uint32_t)((row * CH + ((gg ^ swz) << 2)) * 4);
            int gk = k0 + gg * 4;
            cp16(sb + off,                   Ahi + (size_t)(m0 + row) * K + gk);
            cp16(sb + (uint32_t)T * 4 + off, Bhi + (size_t)(n0 + row) * K + gk);
            if (TERMS >= 2)
                cp16(sb + 2u * T * 4 + off, Blo + (size_t)(n0 + row) * K + gk);
            if (TERMS == 3)
                cp16(sb + 3u * T * 4 + off, Alo + (size_t)(m0 + row) * K + gk);
        }
        asm volatile("cp.async.commit_group;" ::: "memory");
    };

    issue(0);
    issue(1);

    for (int c = 0; c < NC; c++) {
        asm volatile("cp.async.wait_group %0;" :: "n"(STAGES - 2));
        __syncthreads();
        if (c + STAGES - 1 < NC) issue(c + STAGES - 1);

        const uint32_t stb = smb + (uint32_t)((c % STAGES) * SS * 4);
        uint32_t aAh[4], aAl[4], aBh[2], aBl[2];
#pragma unroll
        for (int mt = 0; mt < 4; mt++) {
            int row = wm * 64 + mt * 16 + ao;
            aAh[mt] = stb + (uint32_t)(row * CH * 4);
            if (TERMS == 3) aAl[mt] = aAh[mt] + 3u * T * 4;
        }
#pragma unroll
        for (int ntp = 0; ntp < 2; ntp++) {
            int row = wn * 32 + ntp * 16 + bo;
            aBh[ntp] = stb + (uint32_t)(T * 4 + row * CH * 4);
            if (TERMS >= 2) aBl[ntp] = aBh[ntp] + (uint32_t)(T * 4);
        }

#pragma unroll
        for (int ks = 0; ks < CH / 8; ks++) {
            const uint32_t offA = (uint32_t)(((2 * ks + ak) ^ swzA) << 4);
            const uint32_t offB = (uint32_t)(((2 * ks + bk) ^ swzB) << 4);
            uint32_t afh[4][4], afl[4][4], bfh[4][2], bfl[4][2];
#pragma unroll
            for (int mt = 0; mt < 4; mt++) {
                LDSM4(afh[mt][0], afh[mt][1], afh[mt][2], afh[mt][3], aAh[mt] + offA);
                if (TERMS == 3)
                    LDSM4(afl[mt][0], afl[mt][1], afl[mt][2], afl[mt][3], aAl[mt] + offA);
            }
            LDSM4(bfh[0][0], bfh[0][1], bfh[1][0], bfh[1][1], aBh[0] + offB);
            LDSM4(bfh[2][0], bfh[2][1], bfh[3][0], bfh[3][1], aBh[1] + offB);
            if (TERMS >= 2) {
                LDSM4(bfl[0][0], bfl[0][1], bfl[1][0], bfl[1][1], aBl[0] + offB);
                LDSM4(bfl[2][0], bfl[2][1], bfl[3][0], bfl[3][1], aBl[1] + offB);
            }
#pragma unroll
            for (int mt = 0; mt < 4; mt++)
#pragma unroll
                for (int nt = 0; nt < 4; nt++) {
                    float* a = acc[mt][nt];
                    mma_tf32(a[0], a[1], a[2], a[3],
                             afh[mt][0], afh[mt][1], afh[mt][2], afh[mt][3],
                             bfh[nt][0], bfh[nt][1]);
                    if (TERMS >= 2)
                        mma_tf32(a[0], a[1], a[2], a[3],
                                 afh[mt][0], afh[mt][1], afh[mt][2], afh[mt][3],
                                 bfl[nt][0], bfl[nt][1]);
                    if (TERMS == 3)
                        mma_tf32(a[0], a[1], a[2], a[3],
                                 afl[mt][0], afl[mt][1], afl[mt][2], afl[mt][3],
                                 bfh[nt][0], bfh[nt][1]);
                }
        }
    }

#pragma unroll
    for (int mt = 0; mt < 4; mt++) {
#pragma unroll
        for (int nt = 0; nt < 4; nt++) {
            int row = m0 + wm * 64 + mt * 16 + g;
            int col = n0 + wn * 32 + nt * 8 + ct * 2;
            float v0 = acc[mt][nt][0], v1 = acc[mt][nt][1];
            float v2 = acc[mt][nt][2], v3 = acc[mt][nt][3];
            if (bias) {
                float b0 = bias[col], b1 = bias[col + 1];
                v0 += b0; v1 += b1; v2 += b0; v3 += b1;
            }
            if (do_clip) {
                v0 = fminf(fmaxf(v0, -10.f), 10.f);
                v1 = fminf(fmaxf(v1, -10.f), 10.f);
                v2 = fminf(fmaxf(v2, -10.f), 10.f);
                v3 = fminf(fmaxf(v3, -10.f), 10.f);
            }
            float2 lo2; lo2.x = v0; lo2.y = v1;
            float2 hi2; hi2.x = v2; hi2.y = v3;
            *(float2*)(C + (size_t)row * ldc + col) = lo2;
            *(float2*)(C + (size_t)(row + 8) * ldc + col) = hi2;
        }
    }
}

// q only: [8192 x 768], 3-term tf32 (top-k safe)
__global__ __launch_bounds__(256, 2) void q_gemm(
    const float* __restrict__ xhi, const float* __restrict__ xlo,
    const float* __restrict__ wTh, const float* __restrict__ wTl,
    float* __restrict__ C)
{
    extern __shared__ float sm[];
    gemm_body<3, 16>(xhi, xlo, wTh, wTl, C, CDIM, CDIM, nullptr, 0, sm);
}

__global__ __launch_bounds__(256, 2) void proj_gemm(
    const float* __restrict__ A, const float* __restrict__ Bh,
    const float* __restrict__ Bl, const float* __restrict__ bias,
    float* __restrict__ C)
{
    extern __shared__ float sm[];
    gemm_body<2, 16>(A, nullptr, Bh, Bl, C, CDIM, CDIM, bias, 1, sm);
}

// ============================================================================
// Gather-GEMM: per (b,h) compute Ksel = x[keep]·w_k[h], Vsel = x[keep]·w_v[h].
// ============================================================================
__global__ __launch_bounds__(256, 2) void kvg_gemm(
    const float* __restrict__ xhi, const float* __restrict__ wTh,
    const int* __restrict__ keep,
    float* __restrict__ ksel, float* __restrict__ vselT)
{
    extern __shared__ float sm[];
    constexpr int CH = 32, STAGES = 3;
    constexpr int T  = 128 * CH;
    constexpr int SS = 2 * T;

    const int tid = threadIdx.x, lane = tid & 31, wid = tid >> 5;
    const int g = lane >> 2, ct = lane & 3;
    const int wm = wid & 1, wn = wid >> 1;
    const int m0 = blockIdx.x * 128;
    const int bh = blockIdx.y, b = bh / NH, h = bh % NH;

    const int ao = ((lane >> 3) & 1) * 8 + (lane & 7);
    const int ak = lane >> 4;
    const int bo = (lane >> 4) * 8 + (lane & 7);
    const int bk = (lane >> 3) & 1;
    const int swzA = ao & 7;
    const int swzB = bo & 7;

    const int lrow = tid >> 3, lgg = tid & 7;
    const float* aptr[4];
    const float* bptr[4];
    uint32_t soff[4];
#pragma unroll
    for (int j = 0; j < 4; j++) {
        int row = lrow + 32 * j;
        int tok = keep[bh * KEEP + m0 + row];
        aptr[j] = xhi + (size_t)(b * NTOK + tok) * CDIM + lgg * 4;
        int wrow = (row < 64) ? (CDIM + h * HD + row) : (2 * CDIM + h * HD + row - 64);
        bptr[j] = wTh + (size_t)wrow * CDIM + lgg * 4;
        soff[j] = (uint32_t)((row * CH + ((lgg ^ (row & 7)) << 2)) * 4);
    }

    float acc[4][4][4];
#pragma unroll
    for (int mt = 0; mt < 4; mt++)
#pragma unroll
        for (int nt = 0; nt < 4; nt++)
#pragma unroll
            for (int i = 0; i < 4; i++) acc[mt][nt][i] = 0.f;

    const uint32_t smb = smem_u32(sm);
    const int NC = CDIM / CH;

    auto issue = [&](int c) {
        const uint32_t sb = smb + (uint32_t)((c % STAGES) * SS * 4);
        const int k0 = c * CH;
#pragma unroll
        for (int j = 0; j < 4; j++) {
            cp16(sb + soff[j],                   aptr[j] + k0);
            cp16(sb + (uint32_t)T * 4 + soff[j], bptr[j] + k0);
        }
        asm volatile("cp.async.commit_group;" ::: "memory");
    };

    issue(0);
    issue(1);

    for (int c = 0; c < NC; c++) {
        asm volatile("cp.async.wait_group %0;" :: "n"(STAGES - 2));
        __syncthreads();
        if (c + STAGES - 1 < NC) issue(c + STAGES - 1);

        const uint32_t stb = smb + (uint32_t)((c % STAGES) * SS * 4);
        uint32_t aA[4], aB[2];
#pragma unroll
        for (int mt = 0; mt < 4; mt++)
            aA[mt] = stb + (uint32_t)((wm * 64 + mt * 16 + ao) * CH * 4);
#pragma unroll
        for (int ntp = 0; ntp < 2; ntp++)
            aB[ntp] = stb + (uint32_t)(T * 4 + (wn * 32 + ntp * 16 + bo) * CH * 4);

#pragma unroll
        for (int ks = 0; ks < CH / 8; ks++) {
            const uint32_t offA = (uint32_t)(((2 * ks + ak) ^ swzA) << 4);
            const uint32_t offB = (uint32_t)(((2 * ks + bk) ^ swzB) << 4);
            uint32_t af[4][4], bf[4][2];
#pragma unroll
            for (int mt = 0; mt < 4; mt++)
                LDSM4(af[mt][0], af[mt][1], af[mt][2], af[mt][3], aA[mt] + offA);
            LDSM4(bf[0][0], bf[0][1], bf[1][0], bf[1][1], aB[0] + offB);
            LDSM4(bf[2][0], bf[2][1], bf[3][0], bf[3][1], aB[1] + offB);
#pragma unroll
            for (int mt = 0; mt < 4; mt++)
#pragma unroll
                for (int nt = 0; nt < 4; nt++)
                    mma_tf32(acc[mt][nt][0], acc[mt][nt][1], acc[mt][nt][2], acc[mt][nt][3],
                             af[mt][0], af[mt][1], af[mt][2], af[mt][3],
                             bf[nt][0], bf[nt][1]);
        }
    }

    __syncthreads();

    if (wn < 2) {
#pragma unroll
        for (int mt = 0; mt < 4; mt++) {
#pragma unroll
            for (int nt = 0; nt < 4; nt++) {
                int j0 = wm * 64 + mt * 16 + g;
                int d  = wn * 32 + nt * 8 + ct * 2;
                float2 a;
                a.x = tf32_rna(acc[mt][nt][0]); a.y = tf32_rna(acc[mt][nt][1]);
                *(float2*)(ksel + ((size_t)bh * KEEP + m0 + j0) * HD + d) = a;
                float2 c2;
                c2.x = tf32_rna(acc[mt][nt][2]); c2.y = tf32_rna(acc[mt][nt][3]);
                *(float2*)(ksel + ((size_t)bh * KEEP + m0 + j0 + 8) * HD + d) = c2;
            }
        }
    } else {
        float* vst = sm;   // [64][132]
#pragma unroll
        for (int mt = 0; mt < 4; mt++) {
#pragma unroll
            for (int nt = 0; nt < 4; nt++) {
                int j0 = wm * 64 + mt * 16 + g;
                int j1 = j0 + 8;
                int d  = (wn - 2) * 32 + nt * 8 + ct * 2;
                int s0 = (j0 & ~7) | ((j0 & 1) << 2) | ((j0 & 7) >> 1);
                int s1 = (j1 & ~7) | ((j1 & 1) << 2) | ((j1 & 7) >> 1);
                vst[d * 132 + s0]       = tf32_rna(acc[mt][nt][0]);
                vst[(d + 1) * 132 + s0] = tf32_rna(acc[mt][nt][1]);
                vst[d * 132 + s1]       = tf32_rna(acc[mt][nt][2]);
                vst[(d + 1) * 132 + s1] = tf32_rna(acc[mt][nt][3]);
            }
        }
    }
    __syncthreads();

    for (int i = tid; i < 64 * 32; i += 256) {
        int d = i >> 5, f = (i & 31) * 4;
        float4 v;
        v.x = sm[d * 132 + f];     v.y = sm[d * 132 + f + 1];
        v.z = sm[d * 132 + f + 2]; v.w = sm[d * 132 + f + 3];
        *(float4*)(vselT + ((size_t)bh * HD + d) * KEEP + m0 + f) = v;
    }
}

// ============================================================================
// x -> (hi, lo) tf32 split
// ============================================================================
__global__ void xsplit_kernel(const float* __restrict__ x, float* __restrict__ hi,
                              float* __restrict__ lo, int n4)
{
    int i = blockIdx.x * blockDim.x + threadIdx.x;
    if (i >= n4) return;
    float4 v = ((const float4*)x)[i];
    float4 h, l;
    h.x = tf32_rna(v.x); l.x = tf32_rna(v.x - h.x);
    h.y = tf32_rna(v.y); l.y = tf32_rna(v.y - h.y);
    h.z = tf32_rna(v.z); l.z = tf32_rna(v.z - h.z);
    h.w = tf32_rna(v.w); l.w = tf32_rna(v.w - h.w);
    ((float4*)hi)[i] = h;
    ((float4*)lo)[i] = l;
}

// ============================================================================
// combined weight transpose + tf32 split: both w_qkv and w_proj in one launch
// ============================================================================
__global__ void wsplit_kernel(const float* __restrict__ in1, float* __restrict__ ohi1,
                              float* __restrict__ olo1,
                              const float* __restrict__ in2, float* __restrict__ ohi2,
                              float* __restrict__ olo2)
{
    __shared__ float t[32][33];
    const int K = CDIM;
    const float* in; float *ohi, *olo; int n0;
    if (blockIdx.x < C3 / 32) {
        in = in1; ohi = ohi1; olo = olo1; n0 = blockIdx.x * 32;
    } else {
        in = in2; ohi = ohi2; olo = olo2; n0 = (blockIdx.x - C3 / 32) * 32;
    }
    const int N = (blockIdx.x < C3 / 32) ? C3 : CDIM;
    const int k0 = blockIdx.y * 32;
    const int tx = threadIdx.x, ty = threadIdx.y;
#pragma unroll
    for (int i = 0; i < 4; i++)
        t[ty + i * 8][tx] = in[(size_t)(k0 + ty + i * 8) * N + n0 + tx];
    __syncthreads();
#pragma unroll
    for (int i = 0; i < 4; i++) {
        float v = t[tx][ty + i * 8];
        float h = tf32_rna(v);
        ohi[(size_t)(n0 + ty + i * 8) * K + k0 + tx] = h;
        olo[(size_t)(n0 + ty + i * 8) * K + k0 + tx] = tf32_rna(v - h);
    }
}

// ============================================================================
// scores[bh][n] = sum_d q^2  (full-chip grid: bandwidth-optimal)
// ============================================================================
__global__ void scores_kernel(const float* __restrict__ q, float* __restrict__ scores)
{
    int idx = blockIdx.x * blockDim.x + threadIdx.x;
    if (idx >= NBH * NTOK) return;
    int n  = idx & (NTOK - 1);
    int bh = idx >> 11;
    int h = bh % NH, b = bh / NH;
    const float4* qp = (const float4*)(q + (size_t)(b * NTOK + n) * CDIM + h * HD);
    float s = 0.f;
#pragma unroll
    for (int u = 0; u < 16; u++) {
        float4 v = qp[u];
        s += v.x * v.x + v.y * v.y + v.z * v.z + v.w * v.w;
    }
    scores[idx] = s;
}

// ============================================================================
// Per-(b,h) top-KEEP via bitonic sort of packed u64 keys (set semantics).
// ============================================================================
__global__ __launch_bounds__(1024) void topk_kernel(
    const float* __restrict__ scores, int* __restrict__ keep)
{
    __shared__ unsigned long long keys[NTOK];
    const int bh = blockIdx.x, t = threadIdx.x;
    for (int i = t; i < NTOK; i += 1024) {
        unsigned sb = __float_as_uint(scores[bh * NTOK + i]);
        keys[i] = ((unsigned long long)sb << 32) | (unsigned)(NTOK - 1 - i);
    }
    for (int k = 2; k <= NTOK; k <<= 1) {
        for (int j = k >> 1; j > 0; j >>= 1) {
            __syncthreads();
            for (int i = t; i < NTOK; i += 1024) {
                int ixj = i ^ j;
                if (ixj > i) {
                    unsigned long long a = keys[i], c = keys[ixj];
                    bool asc = ((i & k) == 0);
                    if ((a > c) == asc) { keys[i] = c; keys[ixj] = a; }
                }
            }
        }
    }
    __syncthreads();
    if (t < KEEP) {
        keep[bh * KEEP + t] = (NTOK - 1) - (int)(keys[NTOK - KEEP + t] & 0xffffffffu);
    }
}

// ============================================================================
// mma.sync attention (R11 proven config): warp-row-split + 2-stage cp.async,
// key chunks of 64, P in registers, V pre-permuted. smem 96KB, 2 CTAs/SM.
// ============================================================================
__global__ __launch_bounds__(256, 2) void attn_mma(
    const float* __restrict__ q, const float* __restrict__ ksel,
    const float* __restrict__ vselT, float* __restrict__ out)
{
    extern __shared__ float sm[];
    float* Qs = sm;
    const uint32_t smb    = smem_u32(sm);
    const uint32_t stage0 = smb + 8192u * 4;

    const int tid = threadIdx.x, lane = tid & 31, wid = tid >> 5;
    const int g = lane >> 2, ct = lane & 3;
    const int bh = blockIdx.y, b = bh / NH, h = bh % NH;
    const int qbase = blockIdx.x * 128;

    const int ao = ((lane >> 3) & 1) * 8 + (lane & 7);
    const int ak = lane >> 4;
    const int bo = (lane >> 4) * 8 + (lane & 7);
    const int bk = (lane >> 3) & 1;
    const int swzq = ao & 7;
    const int swzb = bo & 7;

    {
        int j = tid & 127, half = tid >> 7;
        const float* qrow = q + (size_t)(b * NTOK + qbase + j) * CDIM + h * HD + half * 32;
        const float QSC = 0.125f * 1.44269504f;
#pragma unroll
        for (int i = 0; i < 8; i++) {
            float4 v = *(const float4*)(qrow + i * 4);
            v.x = tf32_rna(v.x * QSC); v.y = tf32_rna(v.y * QSC);
            v.z = tf32_rna(v.z * QSC); v.w = tf32_rna(v.w * QSC);
            int c = half * 32 + i * 4;
            *(float4*)&Qs[j * 64 + (c ^ ((j & 7) << 2))] = v;
        }
    }

    const float* kbase = ksel  + (size_t)bh * KEEP * HD;
    const float* vbase = vselT + (size_t)bh * HD * KEEP;

    auto issue = [&](int kc) {
        const uint32_t sb = stage0 + (uint32_t)((kc & 1) * 8192 * 4);
#pragma unroll
        for (int j = 0; j < 4; j++) {
            int gidx = tid + j * 256;
            int row = gidx >> 4, gg = gidx & 15;
            uint32_t off = (uint32_t)((row * 64 + ((gg ^ (row & 7)) << 2)) * 4);
            cp16(sb + off, kbase + (size_t)(kc * 64 + row) * HD + gg * 4);
            cp16(sb + 4096u * 4 + off, vbase + (size_t)row * KEEP + kc * 64 + gg * 4);
        }
        asm volatile("cp.async.commit_group;" ::: "memory");
    };

    const uint32_t qa_base = smb + (uint32_t)((wid * 16 + ao) * 64 * 4);

    float P[8][4];
    float O[8][4];
    float lp0 = 0.f, lp1 = 0.f;
#pragma unroll
    for (int dt = 0; dt < 8; dt++)
#pragma unroll
        for (int i = 0; i < 4; i++) O[dt][i] = 0.f;

    issue(0);

    for (int kc = 0; kc < KEEP / 64; kc++) {
        if (kc + 1 < KEEP / 64) {
            issue(kc + 1);
            asm volatile("cp.async.wait_group 1;" ::: "memory");
        } else {
            asm volatile("cp.async.wait_group 0;" ::: "memory");
        }
        __syncthreads();

        const uint32_t kst = stage0 + (uint32_t)((kc & 1) * 8192 * 4);
        const uint32_t vst = kst + 4096u * 4;

#pragma unroll
        for (int nt = 0; nt < 8; nt++)
#pragma unroll
            for (int i = 0; i < 4; i++) P[nt][i] = 0.f;

#pragma unroll
        for (int ks = 0; ks < 8; ks++) {
            const uint32_t offq = (uint32_t)(((2 * ks + ak) ^ swzq) << 4);
            const uint32_t offb = (uint32_t)(((2 * ks + bk) ^ swzb) << 4);
            uint32_t qa0, qa1, qa2, qa3;
            LDSM4(qa0, qa1, qa2, qa3, qa_base + offq);
#pragma unroll
            for (int ntp = 0; ntp < 4; ntp++) {
                uint32_t k00, k01, k10, k11;
                LDSM4(k00, k01, k10, k11, kst + (uint32_t)((ntp * 16 + bo) * 64 * 4) + offb);
                mma_tf32(P[2 * ntp][0], P[2 * ntp][1], P[2 * ntp][2], P[2 * ntp][3],
                         qa0, qa1, qa2, qa3, k00, k01);
                mma_tf32(P[2 * ntp + 1][0], P[2 * ntp + 1][1], P[2 * ntp + 1][2], P[2 * ntp + 1][3],
                         qa0, qa1, qa2, qa3, k10, k11);
            }
        }

#pragma unroll
        for (int nt = 0; nt < 8; nt++) {
            float p0 = pexp(P[nt][0]);
            float p1 = pexp(P[nt][1]);
            float p2 = pexp(P[nt][2]);
            float p3 = pexp(P[nt][3]);
            lp0 += p0 + p1;
            lp1 += p2 + p3;
            P[nt][0] = p0; P[nt][1] = p1; P[nt][2] = p2; P[nt][3] = p3;
        }

#pragma unroll
        for (int ks = 0; ks < 8; ks++) {
            const uint32_t offv = (uint32_t)(((2 * ks + bk) ^ swzb) << 4);
            uint32_t a0 = __float_as_uint(P[ks][0]);
            uint32_t a1 = __float_as_uint(P[ks][2]);
            uint32_t a2 = __float_as_uint(P[ks][1]);
            uint32_t a3 = __float_as_uint(P[ks][3]);
#pragma unroll
            for (int dtp = 0; dtp < 4; dtp++) {
                uint32_t v00, v01, v10, v11;
                LDSM4(v00, v01, v10, v11, vst + (uint32_t)((dtp * 16 + bo) * 64 * 4) + offv);
                mma_tf32(O[2 * dtp][0], O[2 * dtp][1], O[2 * dtp][2], O[2 * dtp][3],
                         a0, a1, a2, a3, v00, v01);
                mma_tf32(O[2 * dtp + 1][0], O[2 * dtp + 1][1], O[2 * dtp + 1][2], O[2 * dtp + 1][3],
                         a0, a1, a2, a3, v10, v11);
            }
        }
        __syncthreads();
    }

    lp0 += __shfl_xor_sync(0xffffffffu, lp0, 1);
    lp0 += __shfl_xor_sync(0xffffffffu, lp0, 2);
    lp1 += __shfl_xor_sync(0xffffffffu, lp1, 1);
    lp1 += __shfl_xor_sync(0xffffffffu, lp1, 2);
    const float li0 = 1.f / lp0, li1 = 1.f / lp1;

    const int row0 = qbase + wid * 16 + g;
#pragma unroll
    for (int dt = 0; dt < 8; dt++) {
        int d0 = dt * 8 + 2 * ct;
        float2 a;
        a.x = tf32_rna(O[dt][0] * li0);
        a.y = tf32_rna(O[dt][1] * li0);
        *(float2*)&out[(size_t)(b * NTOK + row0) * CDIM + h * HD + d0] = a;
        float2 c;
        c.x = tf32_rna(O[dt][2] * li1);
        c.y = tf32_rna(O[dt][3] * li1);
        *(float2*)&out[(size_t)(b * NTOK + row0 + 8) * CDIM + h * HD + d0] = c;
    }
}

// ============================================================================
// launch
// ============================================================================
extern "C" void kernel_launch(void* const* d_in, const int* in_sizes, int n_in,
                              void* d_out, int out_size)
{
    (void)in_sizes; (void)n_in; (void)out_size;
    const float* x      = (const float*)d_in[0];
    const float* w_qkv  = (const float*)d_in[1];
    const float* w_proj = (const float*)d_in[2];
    const float* b_proj = (const float*)d_in[3];
    float* out = (float*)d_out;

    float *q_p, *sc_p, *ks_p, *vT_p, *ao_p, *xhi_p, *xlo_p;
    float *wqh_p, *wql_p, *wph_p, *wpl_p;
    int* keep_p;
    cudaGetSymbolAddress((void**)&q_p,    g_q);
    cudaGetSymbolAddress((void**)&sc_p,   g_scores);
    cudaGetSymbolAddress((void**)&keep_p, g_keep);
    cudaGetSymbolAddress((void**)&ks_p,   g_ksel);
    cudaGetSymbolAddress((void**)&vT_p,   g_vselT);
    cudaGetSymbolAddress((void**)&ao_p,   g_attnout);
    cudaGetSymbolAddress((void**)&xhi_p,  g_xhi);
    cudaGetSymbolAddress((void**)&xlo_p,  g_xlo);
    cudaGetSymbolAddress((void**)&wqh_p,  g_wqT_hi);
    cudaGetSymbolAddress((void**)&wql_p,  g_wqT_lo);
    cudaGetSymbolAddress((void**)&wph_p,  g_wpT_hi);
    cudaGetSymbolAddress((void**)&wpl_p,  g_wpT_lo);

    const int smem_q    = 3 * 8192 * (int)sizeof(float);   // 98304
    const int smem_proj = 3 * 6144 * (int)sizeof(float);   // 73728
    const int smem_kvg  = 3 * 8192 * (int)sizeof(float);   // 98304
    cudaFuncSetAttribute(q_gemm,    cudaFuncAttributeMaxDynamicSharedMemorySize, smem_q);
    cudaFuncSetAttribute(proj_gemm, cudaFuncAttributeMaxDynamicSharedMemorySize, smem_proj);
    cudaFuncSetAttribute(kvg_gemm,  cudaFuncAttributeMaxDynamicSharedMemorySize, smem_kvg);
    const int attn_smem = 3 * 8192 * (int)sizeof(float);   // 98304
    cudaFuncSetAttribute(attn_mma, cudaFuncAttributeMaxDynamicSharedMemorySize, attn_smem);

    // 0) tf32 splits (weights merged into one launch)
    xsplit_kernel<<<(ROWS * CDIM / 4 + 255) / 256, 256>>>(x, xhi_p, xlo_p, ROWS * CDIM / 4);
    wsplit_kernel<<<dim3(C3 / 32 + CDIM / 32, CDIM / 32), dim3(32, 8)>>>(
        w_qkv, wqh_p, wql_p, w_proj, wph_p, wpl_p);

    // 1) q = x @ w_q  (3-term tf32)
    q_gemm<<<dim3(CDIM / 128, ROWS / 128), 256, smem_q>>>(
        xhi_p, xlo_p, wqh_p, wql_p, q_p);

    // 2) scores (full-chip grid) then top-k (sort only)
    scores_kernel<<<(NBH * NTOK + 255) / 256, 256>>>(q_p, sc_p);
    topk_kernel<<<NBH, 1024>>>(sc_p, keep_p);

    // 3) gather-GEMM: Ksel / Vsel^T for selected tokens only
    kvg_gemm<<<dim3(KEEP / 128, NBH), 256, smem_kvg>>>(
        xhi_p, wqh_p, keep_p, ks_p, vT_p);

    // 4) attention on tensor cores (chunk 64, 2 CTAs/SM — proven R11 config)
    attn_mma<<<dim3(NTOK / 128, NBH), 256, attn_smem>>>(q_p, ks_p, vT_p, ao_p);

    // 5) out = clip(attnout @ w_proj + b_proj, -10, 10)
    proj_gemm<<<dim3(CDIM / 128, ROWS / 128), 256, smem_proj>>>(
        ao_p, wph_p, wpl_p, b_proj, out);
}

// round 15
// speedup vs baseline: 1.0649x; 1.0216x over previous
#include <cuda_runtime.h>
#include <math.h>
#include <cstdint>

#define NH    12
#define NTOK  2048
#define BATCH 4
#define CDIM  768
#define HD    64
#define KEEP  1024
#define ROWS  (BATCH*NTOK)   /* 8192 */
#define C3    (3*CDIM)       /* 2304 */
#define NBH   (BATCH*NH)     /* 48 */
#define CLIPV 72.134689f     /* 50 * log2(e) */

// ---- scratch (static device globals; no runtime allocation) ----
__device__ float g_q[(size_t)ROWS * CDIM];          // q only, [row][768]
__device__ float g_scores2[(size_t)ROWS * NH * 2];  // per-(row,head) 2-slot partial sums
__device__ int   g_keep[NBH * KEEP];
__device__ float g_ksel [(size_t)NBH * KEEP * HD];  // [bh][j][d] row-major, tf32
__device__ float g_vselT[(size_t)NBH * HD * KEEP];  // [bh][d][slot] transposed+permuted
__device__ float g_attnout[(size_t)ROWS * CDIM];
__device__ float g_xhi[(size_t)ROWS * CDIM];
__device__ float g_xlo[(size_t)ROWS * CDIM];
__device__ float g_wqT_hi[(size_t)C3 * CDIM];       // w_qkv^T [2304][768]
__device__ float g_wqT_lo[(size_t)C3 * CDIM];
__device__ float g_wpT_hi[(size_t)CDIM * CDIM];
__device__ float g_wpT_lo[(size_t)CDIM * CDIM];

__device__ __forceinline__ float tf32_rna(float a) {
    float r; asm("cvt.rna.tf32.f32 %0, %1;" : "=f"(r) : "f"(a)); return r;
}
__device__ __forceinline__ float pexp(float s) {
    s = fminf(fmaxf(s, -CLIPV), CLIPV);
    float r; asm("ex2.approx.ftz.f32 %0, %1;" : "=f"(r) : "f"(s)); return r;
}
__device__ __forceinline__ uint32_t smem_u32(const void* p) {
    uint32_t a;
    asm("{ .reg .u64 t; cvta.to.shared.u64 t, %1; cvt.u32.u64 %0, t; }" : "=r"(a) : "l"(p));
    return a;
}
__device__ __forceinline__ void cp16(uint32_t dst, const float* src) {
    size_t ga = __cvta_generic_to_global(src);
    asm volatile("cp.async.cg.shared.global [%0], [%1], 16;" :: "r"(dst), "l"(ga));
}
__device__ __forceinline__ void mma_tf32(float& c0, float& c1, float& c2, float& c3,
                                         uint32_t a0, uint32_t a1, uint32_t a2, uint32_t a3,
                                         uint32_t b0, uint32_t b1) {
    asm volatile("mma.sync.aligned.m16n8k8.row.col.f32.tf32.tf32.f32 "
        "{%0,%1,%2,%3}, {%4,%5,%6,%7}, {%8,%9}, {%0,%1,%2,%3};"
        : "+f"(c0), "+f"(c1), "+f"(c2), "+f"(c3)
        : "r"(a0), "r"(a1), "r"(a2), "r"(a3), "r"(b0), "r"(b1));
}
#define LDSM4(r0_, r1_, r2_, r3_, addr_) \
    asm volatile("ldmatrix.sync.aligned.m8n8.x4.shared.b16 {%0,%1,%2,%3}, [%4];" \
        : "=r"(r0_), "=r"(r1_), "=r"(r2_), "=r"(r3_) : "r"(addr_) )

// ============================================================================
// 3-stage cp.async mma.sync tf32 GEMM body (dense), ldmatrix feeds.
// C[M,N] = A[M,K] @ BT[N,K]^T, CTA tile 128x128, 8 warps (2m x 4n).
// TERMS=3: Ah*Bh + Ah*Bl + Al*Bh;  TERMS=2: Ah*(Bh+Bl).
// scores2 != nullptr: also emit per-(row,head) sum-of-squares partials
// (deterministic two-slot layout [row][head][wn&1]).
// ============================================================================
template<int TERMS, int CH>
__device__ __forceinline__ void gemm_body(
    const float* __restrict__ Ahi, const float* __restrict__ Alo,
    const float* __restrict__ Bhi, const float* __restrict__ Blo,
    float* __restrict__ C, int K, int ldc,
    const float* __restrict__ bias, int do_clip, float* sm,
    float* __restrict__ scores2)
{
    constexpr int STAGES = 3;
    constexpr int T  = 128 * CH;
    constexpr int NT = (TERMS == 3) ? 4 : (TERMS + 1);
    constexpr int SS = NT * T;
    constexpr int GPR = CH / 4;
    constexpr int GPT = 128 * GPR / 256;

    const int tid = threadIdx.x, lane = tid & 31, wid = tid >> 5;
    const int g = lane >> 2, ct = lane & 3;
    const int wm = wid & 1, wn = wid >> 1;
    const int m0 = blockIdx.y * 128, n0 = blockIdx.x * 128;

    const int ao = ((lane >> 3) & 1) * 8 + (lane & 7);
    const int ak = lane >> 4;
    const int bo = (lane >> 4) * 8 + (lane & 7);
    const int bk = (lane >> 3) & 1;
    const int swzA = (CH == 16) ? ((ao >> 1) & 3) : (ao & 7);
    const int swzB = (CH == 16) ? ((bo >> 1) & 3) : (bo & 7);

    float acc[4][4][4];
#pragma unroll
    for (int mt = 0; mt < 4; mt++)
#pragma unroll
        for (int nt = 0; nt < 4; nt++)
#pragma unroll
            for (int i = 0; i < 4; i++) acc[mt][nt][i] = 0.f;

    const uint32_t smb = smem_u32(sm);
    const int NC = K / CH;

    auto issue = [&](int c) {
        const uint32_t sb = smb + (uint32_t)((c % STAGES) * SS * 4);
        const int k0 = c * CH;
#pragma unroll
        for (int j = 0; j < GPT; j++) {
            int gidx = tid + j * 256;
            int row = gidx / GPR, gg = gidx & (GPR - 1);
            int swz = (CH == 16) ? ((row >> 1) & 3) : (row & 7);
            uint32_t off = (uint32_t)((row * CH + ((gg ^ swz) << 2)) * 4);
            int gk = k0 + gg * 4;
            cp16(sb + off,                   Ahi + (size_t)(m0 + row) * K + gk);
            cp16(sb + (uint32_t)T * 4 + off, Bhi + (size_t)(n0 + row) * K + gk);
            if (TERMS >= 2)
                cp16(sb + 2u * T * 4 + off, Blo + (size_t)(n0 + row) * K + gk);
            if (TERMS == 3)
                cp16(sb + 3u * T * 4 + off, Alo + (size_t)(m0 + row) * K + gk);
        }
        asm volatile("cp.async.commit_group;" ::: "memory");
    };

    issue(0);
    issue(1);

    for (int c = 0; c < NC; c++) {
        asm volatile("cp.async.wait_group %0;" :: "n"(STAGES - 2));
        __syncthreads();
        if (c + STAGES - 1 < NC) issue(c + STAGES - 1);

        const uint32_t stb = smb + (uint32_t)((c % STAGES) * SS * 4);
        uint32_t aAh[4], aAl[4], aBh[2], aBl[2];
#pragma unroll
        for (int mt = 0; mt < 4; mt++) {
            int row = wm * 64 + mt * 16 + ao;
            aAh[mt] = stb + (uint32_t)(row * CH * 4);
            if (TERMS == 3) aAl[mt] = aAh[mt] + 3u * T * 4;
        }
#pragma unroll
        for (int ntp = 0; ntp < 2; ntp++) {
            int row = wn * 32 + ntp * 16 + bo;
            aBh[ntp] = stb + (uint32_t)(T * 4 + row * CH * 4);
            if (TERMS >= 2) aBl[ntp] = aBh[ntp] + (uint32_t)(T * 4);
        }

#pragma unroll
        for (int ks = 0; ks < CH / 8; ks++) {
            const uint32_t offA = (uint32_t)(((2 * ks + ak) ^ swzA) << 4);
            const uint32_t offB = (uint32_t)(((2 * ks + bk) ^ swzB) << 4);
            uint32_t afh[4][4], afl[4][4], bfh[4][2], bfl[4][2];
#pragma unroll
            for (int mt = 0; mt < 4; mt++) {
                LDSM4(afh[mt][0], afh[mt][1], afh[mt][2], afh[mt][3], aAh[mt] + offA);
                if (TERMS == 3)
                    LDSM4(afl[mt][0], afl[mt][1], afl[mt][2], afl[mt][3], aAl[mt] + offA);
            }
            LDSM4(bfh[0][0], bfh[0][1], bfh[1][0], bfh[1][1], aBh[0] + offB);
            LDSM4(bfh[2][0], bfh[2][1], bfh[3][0], bfh[3][1], aBh[1] + offB);
            if (TERMS >= 2) {
                LDSM4(bfl[0][0], bfl[0][1], bfl[1][0], bfl[1][1], aBl[0] + offB);
                LDSM4(bfl[2][0], bfl[2][1], bfl[3][0], bfl[3][1], aBl[1] + offB);
            }
#pragma unroll
            for (int mt = 0; mt < 4; mt++)
#pragma unroll
                for (int nt = 0; nt < 4; nt++) {
                    float* a = acc[mt][nt];
                    mma_tf32(a[0], a[1], a[2], a[3],
                             afh[mt][0], afh[mt][1], afh[mt][2], afh[mt][3],
                             bfh[nt][0], bfh[nt][1]);
                    if (TERMS >= 2)
                        mma_tf32(a[0], a[1], a[2], a[3],
                                 afh[mt][0], afh[mt][1], afh[mt][2], afh[mt][3],
                                 bfl[nt][0], bfl[nt][1]);
                    if (TERMS == 3)
                        mma_tf32(a[0], a[1], a[2], a[3],
                                 afl[mt][0], afl[mt][1], afl[mt][2], afl[mt][3],
                                 bfh[nt][0], bfh[nt][1]);
                }
        }
    }

#pragma unroll
    for (int mt = 0; mt < 4; mt++) {
#pragma unroll
        for (int nt = 0; nt < 4; nt++) {
            int row = m0 + wm * 64 + mt * 16 + g;
            int col = n0 + wn * 32 + nt * 8 + ct * 2;
            float v0 = acc[mt][nt][0], v1 = acc[mt][nt][1];
            float v2 = acc[mt][nt][2], v3 = acc[mt][nt][3];
            if (bias) {
                float b0 = bias[col], b1 = bias[col + 1];
                v0 += b0; v1 += b1; v2 += b0; v3 += b1;
            }
            if (do_clip) {
                v0 = fminf(fmaxf(v0, -10.f), 10.f);
                v1 = fminf(fmaxf(v1, -10.f), 10.f);
                v2 = fminf(fmaxf(v2, -10.f), 10.f);
                v3 = fminf(fmaxf(v3, -10.f), 10.f);
            }
            float2 lo2; lo2.x = v0; lo2.y = v1;
            float2 hi2; hi2.x = v2; hi2.y = v3;
            *(float2*)(C + (size_t)row * ldc + col) = lo2;
            *(float2*)(C + (size_t)(row + 8) * ldc + col) = hi2;
        }
    }

    // ---- fused score partials: sumsq over this warp's 32 cols of each row,
    // quad-reduced over ct, written to the (wn&1) slot of (row, head).
    if (scores2) {
        const int head = (n0 >> 6) + (wn >> 1);
        const int slot = wn & 1;
#pragma unroll
        for (int mt = 0; mt < 4; mt++) {
#pragma unroll
            for (int hf = 0; hf < 2; hf++) {
                float s = 0.f;
#pragma unroll
                for (int nt = 0; nt < 4; nt++) {
                    float a = acc[mt][nt][hf * 2 + 0];
                    float b = acc[mt][nt][hf * 2 + 1];
                    s += a * a + b * b;
                }
                s += __shfl_xor_sync(0xffffffffu, s, 1);
                s += __shfl_xor_sync(0xffffffffu, s, 2);
                if (ct == 0) {
                    int row = m0 + wm * 64 + mt * 16 + g + hf * 8;
                    scores2[((size_t)row * NH + head) * 2 + slot] = s;
                }
            }
        }
    }
}

// q only: [8192 x 768], 3-term tf32 (top-k safe) + fused score partials
__global__ __launch_bounds__(256, 2) void q_gemm(
    const float* __restrict__ xhi, const float* __restrict__ xlo,
    const float* __restrict__ wTh, const float* __restrict__ wTl,
    float* __restrict__ C, float* __restrict__ scores2)
{
    extern __shared__ float sm[];
    gemm_body<3, 16>(xhi, xlo, wTh, wTl, C, CDIM, CDIM, nullptr, 0, sm, scores2);
}

__global__ __launch_bounds__(256, 2) void proj_gemm(
    const float* __restrict__ A, const float* __restrict__ Bh,
    const float* __restrict__ Bl, const float* __restrict__ bias,
    float* __restrict__ C)
{
    extern __shared__ float sm[];
    gemm_body<2, 16>(A, nullptr, Bh, Bl, C, CDIM, CDIM, bias, 1, sm, nullptr);
}

// ============================================================================
// Gather-GEMM: per (b,h) compute Ksel = x[keep]·w_k[h], Vsel = x[keep]·w_v[h].
// ============================================================================
__global__ __launch_bounds__(256, 2) void kvg_gemm(
    const float* __restrict__ xhi, const float* __restrict__ wTh,
    const int* __restrict__ keep,
    float* __restrict__ ksel, float* __restrict__ vselT)
{
    extern __shared__ float sm[];
    constexpr int CH = 32, STAGES = 3;
    constexpr int T  = 128 * CH;
    constexpr int SS = 2 * T;

    const int tid = threadIdx.x, lane = tid & 31, wid = tid >> 5;
    const int g = lane >> 2, ct = lane & 3;
    const int wm = wid & 1, wn = wid >> 1;
    const int m0 = blockIdx.x * 128;
    const int bh = blockIdx.y, b = bh / NH, h = bh % NH;

    const int ao = ((lane >> 3) & 1) * 8 + (lane & 7);
    const int ak = lane >> 4;
    const int bo = (lane >> 4) * 8 + (lane & 7);
    const int bk = (lane >> 3) & 1;
    const int swzA = ao & 7;
    const int swzB = bo & 7;

    const int lrow = tid >> 3, lgg = tid & 7;
    const float* aptr[4];
    const float* bptr[4];
    uint32_t soff[4];
#pragma unroll
    for (int j = 0; j < 4; j++) {
        int row = lrow + 32 * j;
        int tok = keep[bh * KEEP + m0 + row];
        aptr[j] = xhi + (size_t)(b * NTOK + tok) * CDIM + lgg * 4;
        int wrow = (row < 64) ? (CDIM + h * HD + row) : (2 * CDIM + h * HD + row - 64);
        bptr[j] = wTh + (size_t)wrow * CDIM + lgg * 4;
        soff[j] = (uint32_t)((row * CH + ((lgg ^ (row & 7)) << 2)) * 4);
    }

    float acc[4][4][4];
#pragma unroll
    for (int mt = 0; mt < 4; mt++)
#pragma unroll
        for (int nt = 0; nt < 4; nt++)
#pragma unroll
            for (int i = 0; i < 4; i++) acc[mt][nt][i] = 0.f;

    const uint32_t smb = smem_u32(sm);
    const int NC = CDIM / CH;

    auto issue = [&](int c) {
        const uint32_t sb = smb + (uint32_t)((c % STAGES) * SS * 4);
        const int k0 = c * CH;
#pragma unroll
        for (int j = 0; j < 4; j++) {
            cp16(sb + soff[j],                   aptr[j] + k0);
            cp16(sb + (uint32_t)T * 4 + soff[j], bptr[j] + k0);
        }
        asm volatile("cp.async.commit_group;" ::: "memory");
    };

    issue(0);
    issue(1);

    for (int c = 0; c < NC; c++) {
        asm volatile("cp.async.wait_group %0;" :: "n"(STAGES - 2));
        __syncthreads();
        if (c + STAGES - 1 < NC) issue(c + STAGES - 1);

        const uint32_t stb = smb + (uint32_t)((c % STAGES) * SS * 4);
        uint32_t aA[4], aB[2];
#pragma unroll
        for (int mt = 0; mt < 4; mt++)
            aA[mt] = stb + (uint32_t)((wm * 64 + mt * 16 + ao) * CH * 4);
#pragma unroll
        for (int ntp = 0; ntp < 2; ntp++)
            aB[ntp] = stb + (uint32_t)(T * 4 + (wn * 32 + ntp * 16 + bo) * CH * 4);

#pragma unroll
        for (int ks = 0; ks < CH / 8; ks++) {
            const uint32_t offA = (uint32_t)(((2 * ks + ak) ^ swzA) << 4);
            const uint32_t offB = (uint32_t)(((2 * ks + bk) ^ swzB) << 4);
            uint32_t af[4][4], bf[4][2];
#pragma unroll
            for (int mt = 0; mt < 4; mt++)
                LDSM4(af[mt][0], af[mt][1], af[mt][2], af[mt][3], aA[mt] + offA);
            LDSM4(bf[0][0], bf[0][1], bf[1][0], bf[1][1], aB[0] + offB);
            LDSM4(bf[2][0], bf[2][1], bf[3][0], bf[3][1], aB[1] + offB);
#pragma unroll
            for (int mt = 0; mt < 4; mt++)
#pragma unroll
                for (int nt = 0; nt < 4; nt++)
                    mma_tf32(acc[mt][nt][0], acc[mt][nt][1], acc[mt][nt][2], acc[mt][nt][3],
                             af[mt][0], af[mt][1], af[mt][2], af[mt][3],
                             bf[nt][0], bf[nt][1]);
        }
    }

    __syncthreads();

    if (wn < 2) {
#pragma unroll
        for (int mt = 0; mt < 4; mt++) {
#pragma unroll
            for (int nt = 0; nt < 4; nt++) {
                int j0 = wm * 64 + mt * 16 + g;
                int d  = wn * 32 + nt * 8 + ct * 2;
                float2 a;
                a.x = tf32_rna(acc[mt][nt][0]); a.y = tf32_rna(acc[mt][nt][1]);
                *(float2*)(ksel + ((size_t)bh * KEEP + m0 + j0) * HD + d) = a;
                float2 c2;
                c2.x = tf32_rna(acc[mt][nt][2]); c2.y = tf32_rna(acc[mt][nt][3]);
                *(float2*)(ksel + ((size_t)bh * KEEP + m0 + j0 + 8) * HD + d) = c2;
            }
        }
    } else {
        float* vst = sm;   // [64][132]
#pragma unroll
        for (int mt = 0; mt < 4; mt++) {
#pragma unroll
            for (int nt = 0; nt < 4; nt++) {
                int j0 = wm * 64 + mt * 16 + g;
                int j1 = j0 + 8;
                int d  = (wn - 2) * 32 + nt * 8 + ct * 2;
                int s0 = (j0 & ~7) | ((j0 & 1) << 2) | ((j0 & 7) >> 1);
                int s1 = (j1 & ~7) | ((j1 & 1) << 2) | ((j1 & 7) >> 1);
                vst[d * 132 + s0]       = tf32_rna(acc[mt][nt][0]);
                vst[(d + 1) * 132 + s0] = tf32_rna(acc[mt][nt][1]);
                vst[d * 132 + s1]       = tf32_rna(acc[mt][nt][2]);
                vst[(d + 1) * 132 + s1] = tf32_rna(acc[mt][nt][3]);
            }
        }
    }
    __syncthreads();

    for (int i = tid; i < 64 * 32; i += 256) {
        int d = i >> 5, f = (i & 31) * 4;
        float4 v;
        v.x = sm[d * 132 + f];     v.y = sm[d * 132 + f + 1];
        v.z = sm[d * 132 + f + 2]; v.w = sm[d * 132 + f + 3];
        *(float4*)(vselT + ((size_t)bh * HD + d) * KEEP + m0 + f) = v;
    }
}

// ============================================================================
// x -> (hi, lo) tf32 split
// ============================================================================
__global__ void xsplit_kernel(const float* __restrict__ x, float* __restrict__ hi,
                              float* __restrict__ lo, int n4)
{
    int i = blockIdx.x * blockDim.x + threadIdx.x;
    if (i >= n4) return;
    float4 v = ((const float4*)x)[i];
    float4 h, l;
    h.x = tf32_rna(v.x); l.x = tf32_rna(v.x - h.x);
    h.y = tf32_rna(v.y); l.y = tf32_rna(v.y - h.y);
    h.z = tf32_rna(v.z); l.z = tf32_rna(v.z - h.z);
    h.w = tf32_rna(v.w); l.w = tf32_rna(v.w - h.w);
    ((float4*)hi)[i] = h;
    ((float4*)lo)[i] = l;
}

// ============================================================================
// combined weight transpose + tf32 split: both w_qkv and w_proj in one launch
// ============================================================================
__global__ void wsplit_kernel(const float* __restrict__ in1, float* __restrict__ ohi1,
                              float* __restrict__ olo1,
                              const float* __restrict__ in2, float* __restrict__ ohi2,
                              float* __restrict__ olo2)
{
    __shared__ float t[32][33];
    const int K = CDIM;
    const float* in; float *ohi, *olo; int n0;
    if (blockIdx.x < C3 / 32) {
        in = in1; ohi = ohi1; olo = olo1; n0 = blockIdx.x * 32;
    } else {
        in = in2; ohi = ohi2; olo = olo2; n0 = (blockIdx.x - C3 / 32) * 32;
    }
    const int N = (blockIdx.x < C3 / 32) ? C3 : CDIM;
    const int k0 = blockIdx.y * 32;
    const int tx = threadIdx.x, ty = threadIdx.y;
#pragma unroll
    for (int i = 0; i < 4; i++)
        t[ty + i * 8][tx] = in[(size_t)(k0 + ty + i * 8) * N + n0 + tx];
    __syncthreads();
#pragma unroll
    for (int i = 0; i < 4; i++) {
        float v = t[tx][ty + i * 8];
        float h = tf32_rna(v);
        ohi[(size_t)(n0 + ty + i * 8) * K + k0 + tx] = h;
        olo[(size_t)(n0 + ty + i * 8) * K + k0 + tx] = tf32_rna(v - h);
    }
}

// ============================================================================
// Per-(b,h) top-KEEP from fused score partials. Bitonic SET selection:
// run the standard network only to k=1024 — the plain direction formula
// ((i&k)==0) sorts half A ascending and half B DESCENDING (bit 10 flips the
// k=1024 merge), then the top-1024 set is elementwise max(keys[i],
// keys[i+1024]) (bitonic split property).
// ============================================================================
__global__ __launch_bounds__(1024) void topk_kernel(
    const float* __restrict__ scores2, int* __restrict__ keep)
{
    __shared__ unsigned long long keys[NTOK];
    const int bh = blockIdx.x, t = threadIdx.x;
    const int h = bh % NH, b = bh / NH;
    for (int i = t; i < NTOK; i += 1024) {
        size_t base = ((size_t)(b * NTOK + i) * NH + h) * 2;
        float s = scores2[base] + scores2[base + 1];
        keys[i] = ((unsigned long long)__float_as_uint(s) << 32) | (unsigned)(NTOK - 1 - i);
    }
    for (int k = 2; k <= 1024; k <<= 1) {
        for (int j = k >> 1; j > 0; j >>= 1) {
            __syncthreads();
            for (int i = t; i < NTOK; i += 1024) {
                int ixj = i ^ j;
                if (ixj > i) {
                    unsigned long long a = keys[i], c = keys[ixj];
                    bool asc = ((i & k) == 0);
                    if ((a > c) == asc) { keys[i] = c; keys[ixj] = a; }
                }
            }
        }
    }
    __syncthreads();
    {
        unsigned long long a = keys[t], c = keys[t + 1024];
        unsigned long long mx = (a > c) ? a : c;
        keep[bh * KEEP + t] = (NTOK - 1) - (int)(mx & 0xffffffffu);
    }
}

// ============================================================================
// mma.sync attention (proven config): warp-row-split + 2-stage cp.async,
// key chunks of 64, P in registers, V pre-permuted. smem 96KB, 2 CTAs/SM.
// ============================================================================
__global__ __launch_bounds__(256, 2) void attn_mma(
    const float* __restrict__ q, const float* __restrict__ ksel,
    const float* __restrict__ vselT, float* __restrict__ out)
{
    extern __shared__ float sm[];
    float* Qs = sm;
    const uint32_t smb    = smem_u32(sm);
    const uint32_t stage0 = smb + 8192u * 4;

    const int tid = threadIdx.x, lane = tid & 31, wid = tid >> 5;
    const int g = lane >> 2, ct = lane & 3;
    const int bh = blockIdx.y, b = bh / NH, h = bh % NH;
    const int qbase = blockIdx.x * 128;

    const int ao = ((lane >> 3) & 1) * 8 + (lane & 7);
    const int ak = lane >> 4;
    const int bo = (lane >> 4) * 8 + (lane & 7);
    const int bk = (lane >> 3) & 1;
    const int swzq = ao & 7;
    const int swzb = bo & 7;

    {
        int j = tid & 127, half = tid >> 7;
        const float* qrow = q + (size_t)(b * NTOK + qbase + j) * CDIM + h * HD + half * 32;
        const float QSC = 0.125f * 1.44269504f;
#pragma unroll
        for (int i = 0; i < 8; i++) {
            float4 v = *(const float4*)(qrow + i * 4);
            v.x = tf32_rna(v.x * QSC); v.y = tf32_rna(v.y * QSC);
            v.z = tf32_rna(v.z * QSC); v.w = tf32_rna(v.w * QSC);
            int c = half * 32 + i * 4;
            *(float4*)&Qs[j * 64 + (c ^ ((j & 7) << 2))] = v;
        }
    }

    const float* kbase = ksel  + (size_t)bh * KEEP * HD;
    const float* vbase = vselT + (size_t)bh * HD * KEEP;

    auto issue = [&](int kc) {
        const uint32_t sb = stage0 + (uint32_t)((kc & 1) * 8192 * 4);
#pragma unroll
        for (int j = 0; j < 4; j++) {
            int gidx = tid + j * 256;
            int row = gidx >> 4, gg = gidx & 15;
            uint32_t off = (uint32_t)((row * 64 + ((gg ^ (row & 7)) << 2)) * 4);
            cp16(sb + off, kbase + (size_t)(kc * 64 + row) * HD + gg * 4);
            cp16(sb + 4096u * 4 + off, vbase + (size_t)row * KEEP + kc * 64 + gg * 4);
        }
        asm volatile("cp.async.commit_group;" ::: "memory");
    };

    const uint32_t qa_base = smb + (uint32_t)((wid * 16 + ao) * 64 * 4);

    float P[8][4];
    float O[8][4];
    float lp0 = 0.f, lp1 = 0.f;
#pragma unroll
    for (int dt = 0; dt < 8; dt++)
#pragma unroll
        for (int i = 0; i < 4; i++) O[dt][i] = 0.f;

    issue(0);

    for (int kc = 0; kc < KEEP / 64; kc++) {
        if (kc + 1 < KEEP / 64) {
            issue(kc + 1);
            asm volatile("cp.async.wait_group 1;" ::: "memory");
        } else {
            asm volatile("cp.async.wait_group 0;" ::: "memory");
        }
        __syncthreads();

        const uint32_t kst = stage0 + (uint32_t)((kc & 1) * 8192 * 4);
        const uint32_t vst = kst + 4096u * 4;

#pragma unroll
        for (int nt = 0; nt < 8; nt++)
#pragma unroll
            for (int i = 0; i < 4; i++) P[nt][i] = 0.f;

#pragma unroll
        for (int ks = 0; ks < 8; ks++) {
            const uint32_t offq = (uint32_t)(((2 * ks + ak) ^ swzq) << 4);
            const uint32_t offb = (uint32_t)(((2 * ks + bk) ^ swzb) << 4);
            uint32_t qa0, qa1, qa2, qa3;
            LDSM4(qa0, qa1, qa2, qa3, qa_base + offq);
#pragma unroll
            for (int ntp = 0; ntp < 4; ntp++) {
                uint32_t k00, k01, k10, k11;
                LDSM4(k00, k01, k10, k11, kst + (uint32_t)((ntp * 16 + bo) * 64 * 4) + offb);
                mma_tf32(P[2 * ntp][0], P[2 * ntp][1], P[2 * ntp][2], P[2 * ntp][3],
                         qa0, qa1, qa2, qa3, k00, k01);
                mma_tf32(P[2 * ntp + 1][0], P[2 * ntp + 1][1], P[2 * ntp + 1][2], P[2 * ntp + 1][3],
                         qa0, qa1, qa2, qa3, k10, k11);
            }
        }

#pragma unroll
        for (int nt = 0; nt < 8; nt++) {
            float p0 = pexp(P[nt][0]);
            float p1 = pexp(P[nt][1]);
            float p2 = pexp(P[nt][2]);
            float p3 = pexp(P[nt][3]);
            lp0 += p0 + p1;
            lp1 += p2 + p3;
            P[nt][0] = p0; P[nt][1] = p1; P[nt][2] = p2; P[nt][3] = p3;
        }

#pragma unroll
        for (int ks = 0; ks < 8; ks++) {
            const uint32_t offv = (uint32_t)(((2 * ks + bk) ^ swzb) << 4);
            uint32_t a0 = __float_as_uint(P[ks][0]);
            uint32_t a1 = __float_as_uint(P[ks][2]);
            uint32_t a2 = __float_as_uint(P[ks][1]);
            uint32_t a3 = __float_as_uint(P[ks][3]);
#pragma unroll
            for (int dtp = 0; dtp < 4; dtp++) {
                uint32_t v00, v01, v10, v11;
                LDSM4(v00, v01, v10, v11, vst + (uint32_t)((dtp * 16 + bo) * 64 * 4) + offv);
                mma_tf32(O[2 * dtp][0], O[2 * dtp][1], O[2 * dtp][2], O[2 * dtp][3],
                         a0, a1, a2, a3, v00, v01);
                mma_tf32(O[2 * dtp + 1][0], O[2 * dtp + 1][1], O[2 * dtp + 1][2], O[2 * dtp + 1][3],
                         a0, a1, a2, a3, v10, v11);
            }
        }
        __syncthreads();
    }

    lp0 += __shfl_xor_sync(0xffffffffu, lp0, 1);
    lp0 += __shfl_xor_sync(0xffffffffu, lp0, 2);
    lp1 += __shfl_xor_sync(0xffffffffu, lp1, 1);
    lp1 += __shfl_xor_sync(0xffffffffu, lp1, 2);
    const float li0 = 1.f / lp0, li1 = 1.f / lp1;

    const int row0 = qbase + wid * 16 + g;
#pragma unroll
    for (int dt = 0; dt < 8; dt++) {
        int d0 = dt * 8 + 2 * ct;
        float2 a;
        a.x = tf32_rna(O[dt][0] * li0);
        a.y = tf32_rna(O[dt][1] * li0);
        *(float2*)&out[(size_t)(b * NTOK + row0) * CDIM + h * HD + d0] = a;
        float2 c;
        c.x = tf32_rna(O[dt][2] * li1);
        c.y = tf32_rna(O[dt][3] * li1);
        *(float2*)&out[(size_t)(b * NTOK + row0 + 8) * CDIM + h * HD + d0] = c;
    }
}

// ============================================================================
// launch
// ============================================================================
extern "C" void kernel_launch(void* const* d_in, const int* in_sizes, int n_in,
                              void* d_out, int out_size)
{
    (void)in_sizes; (void)n_in; (void)out_size;
    const float* x      = (const float*)d_in[0];
    const float* w_qkv  = (const float*)d_in[1];
    const float* w_proj = (const float*)d_in[2];
    const float* b_proj = (const float*)d_in[3];
    float* out = (float*)d_out;

    float *q_p, *sc2_p, *ks_p, *vT_p, *ao_p, *xhi_p, *xlo_p;
    float *wqh_p, *wql_p, *wph_p, *wpl_p;
    int* keep_p;
    cudaGetSymbolAddress((void**)&q_p,    g_q);
    cudaGetSymbolAddress((void**)&sc2_p,  g_scores2);
    cudaGetSymbolAddress((void**)&keep_p, g_keep);
    cudaGetSymbolAddress((void**)&ks_p,   g_ksel);
    cudaGetSymbolAddress((void**)&vT_p,   g_vselT);
    cudaGetSymbolAddress((void**)&ao_p,   g_attnout);
    cudaGetSymbolAddress((void**)&xhi_p,  g_xhi);
    cudaGetSymbolAddress((void**)&xlo_p,  g_xlo);
    cudaGetSymbolAddress((void**)&wqh_p,  g_wqT_hi);
    cudaGetSymbolAddress((void**)&wql_p,  g_wqT_lo);
    cudaGetSymbolAddress((void**)&wph_p,  g_wpT_hi);
    cudaGetSymbolAddress((void**)&wpl_p,  g_wpT_lo);

    const int smem_q    = 3 * 8192 * (int)sizeof(float);   // 98304
    const int smem_proj = 3 * 6144 * (int)sizeof(float);   // 73728
    const int smem_kvg  = 3 * 8192 * (int)sizeof(float);   // 98304
    cudaFuncSetAttribute(q_gemm,    cudaFuncAttributeMaxDynamicSharedMemorySize, smem_q);
    cudaFuncSetAttribute(proj_gemm, cudaFuncAttributeMaxDynamicSharedMemorySize, smem_proj);
    cudaFuncSetAttribute(kvg_gemm,  cudaFuncAttributeMaxDynamicSharedMemorySize, smem_kvg);
    const int attn_smem = 3 * 8192 * (int)sizeof(float);   // 98304
    cudaFuncSetAttribute(attn_mma, cudaFuncAttributeMaxDynamicSharedMemorySize, attn_smem);

    // 0) tf32 splits (weights merged into one launch)
    xsplit_kernel<<<(ROWS * CDIM / 4 + 255) / 256, 256>>>(x, xhi_p, xlo_p, ROWS * CDIM / 4);
    wsplit_kernel<<<dim3(C3 / 32 + CDIM / 32, CDIM / 32), dim3(32, 8)>>>(
        w_qkv, wqh_p, wql_p, w_proj, wph_p, wpl_p);

    // 1) q = x @ w_q  (3-term tf32) + fused deterministic score partials
    q_gemm<<<dim3(CDIM / 128, ROWS / 128), 256, smem_q>>>(
        xhi_p, xlo_p, wqh_p, wql_p, q_p, sc2_p);

    // 2) top-k (bitonic set-selection: halves sorted asc/desc, elementwise max)
    topk_kernel<<<NBH, 1024>>>(sc2_p, keep_p);

    // 3) gather-GEMM: Ksel / Vsel^T for selected tokens only
    kvg_gemm<<<dim3(KEEP / 128, NBH), 256, smem_kvg>>>(
        xhi_p, wqh_p, keep_p, ks_p, vT_p);

    // 4) attention on tensor cores (chunk 64, 2 CTAs/SM)
    attn_mma<<<dim3(NTOK / 128, NBH), 256, attn_smem>>>(q_p, ks_p, vT_p, ao_p);

    // 5) out = clip(attnout @ w_proj + b_proj, -10, 10)
    proj_gemm<<<dim3(CDIM / 128, ROWS / 128), 256, smem_proj>>>(
        ao_p, wph_p, wpl_p, b_proj, out);
}

// round 16
// speedup vs baseline: 1.1718x; 1.1003x over previous
#include <cuda_runtime.h>
#include <math.h>
#include <cstdint>

#define NH    12
#define NTOK  2048
#define BATCH 4
#define CDIM  768
#define HD    64
#define KEEP  1024
#define ROWS  (BATCH*NTOK)   /* 8192 */
#define C3    (3*CDIM)       /* 2304 */
#define NBH   (BATCH*NH)     /* 48 */
#define CLIPV 72.134689f     /* 50 * log2(e) */

// ---- scratch (static device globals; no runtime allocation) ----
__device__ float g_q[(size_t)ROWS * CDIM];          // q only, [row][768]
__device__ float g_scores2[(size_t)ROWS * NH * 2];  // per-(row,head) 2-slot partial sums
__device__ int   g_keep[NBH * KEEP];
__device__ float g_ksel [(size_t)NBH * KEEP * HD];  // [bh][j][d] row-major, tf32
__device__ float g_vselT[(size_t)NBH * HD * KEEP];  // [bh][d][slot] transposed+permuted
__device__ float g_attnout[(size_t)ROWS * CDIM];
__device__ float g_xhi[(size_t)ROWS * CDIM];
__device__ float g_xlo[(size_t)ROWS * CDIM];
__device__ float g_wqT_hi[(size_t)C3 * CDIM];       // w_qkv^T [2304][768]
__device__ float g_wqT_lo[(size_t)C3 * CDIM];
__device__ float g_wpT_hi[(size_t)CDIM * CDIM];
__device__ float g_wpT_lo[(size_t)CDIM * CDIM];

__device__ __forceinline__ float tf32_rna(float a) {
    float r; asm("cvt.rna.tf32.f32 %0, %1;" : "=f"(r) : "f"(a)); return r;
}
__device__ __forceinline__ float pexp(float s) {
    s = fminf(fmaxf(s, -CLIPV), CLIPV);
    float r; asm("ex2.approx.ftz.f32 %0, %1;" : "=f"(r) : "f"(s)); return r;
}
__device__ __forceinline__ uint32_t smem_u32(const void* p) {
    uint32_t a;
    asm("{ .reg .u64 t; cvta.to.shared.u64 t, %1; cvt.u32.u64 %0, t; }" : "=r"(a) : "l"(p));
    return a;
}
__device__ __forceinline__ void cp16(uint32_t dst, const float* src) {
    size_t ga = __cvta_generic_to_global(src);
    asm volatile("cp.async.cg.shared.global [%0], [%1], 16;" :: "r"(dst), "l"(ga));
}
__device__ __forceinline__ void mma_tf32(float& c0, float& c1, float& c2, float& c3,
                                         uint32_t a0, uint32_t a1, uint32_t a2, uint32_t a3,
                                         uint32_t b0, uint32_t b1) {
    asm volatile("mma.sync.aligned.m16n8k8.row.col.f32.tf32.tf32.f32 "
        "{%0,%1,%2,%3}, {%4,%5,%6,%7}, {%8,%9}, {%0,%1,%2,%3};"
        : "+f"(c0), "+f"(c1), "+f"(c2), "+f"(c3)
        : "r"(a0), "r"(a1), "r"(a2), "r"(a3), "r"(b0), "r"(b1));
}
#define LDSM4(r0_, r1_, r2_, r3_, addr_) \
    asm volatile("ldmatrix.sync.aligned.m8n8.x4.shared.b16 {%0,%1,%2,%3}, [%4];" \
        : "=r"(r0_), "=r"(r1_), "=r"(r2_), "=r"(r3_) : "r"(addr_) )

// ============================================================================
// 3-stage cp.async mma.sync tf32 GEMM body (dense), ldmatrix feeds.
// C[M,N] = A[M,K] @ BT[N,K]^T, CTA tile 128x128, 8 warps (2m x 4n).
// TERMS=3: Ah*Bh + Ah*Bl + Al*Bh;  TERMS=2: Ah*(Bh+Bl);  TERMS=1: Ah*Bh.
// scores2 != nullptr: also emit per-(row,head) sum-of-squares partials.
// ============================================================================
template<int TERMS, int CH>
__device__ __forceinline__ void gemm_body(
    const float* __restrict__ Ahi, const float* __restrict__ Alo,
    const float* __restrict__ Bhi, const float* __restrict__ Blo,
    float* __restrict__ C, int K, int ldc,
    const float* __restrict__ bias, int do_clip, float* sm,
    float* __restrict__ scores2)
{
    constexpr int STAGES = 3;
    constexpr int T  = 128 * CH;
    constexpr int NT = (TERMS == 3) ? 4 : (TERMS + 1);
    constexpr int SS = NT * T;
    constexpr int GPR = CH / 4;
    constexpr int GPT = 128 * GPR / 256;

    const int tid = threadIdx.x, lane = tid & 31, wid = tid >> 5;
    const int g = lane >> 2, ct = lane & 3;
    const int wm = wid & 1, wn = wid >> 1;
    const int m0 = blockIdx.y * 128, n0 = blockIdx.x * 128;

    const int ao = ((lane >> 3) & 1) * 8 + (lane & 7);
    const int ak = lane >> 4;
    const int bo = (lane >> 4) * 8 + (lane & 7);
    const int bk = (lane >> 3) & 1;
    const int swzA = (CH == 16) ? ((ao >> 1) & 3) : (ao & 7);
    const int swzB = (CH == 16) ? ((bo >> 1) & 3) : (bo & 7);

    float acc[4][4][4];
#pragma unroll
    for (int mt = 0; mt < 4; mt++)
#pragma unroll
        for (int nt = 0; nt < 4; nt++)
#pragma unroll
            for (int i = 0; i < 4; i++) acc[mt][nt][i] = 0.f;

    const uint32_t smb = smem_u32(sm);
    const int NC = K / CH;

    auto issue = [&](int c) {
        const uint32_t sb = smb + (uint32_t)((c % STAGES) * SS * 4);
        const int k0 = c * CH;
#pragma unroll
        for (int j = 0; j < GPT; j++) {
            int gidx = tid + j * 256;
            int row = gidx / GPR, gg = gidx & (GPR - 1);
            int swz = (CH == 16) ? ((row >> 1) & 3) : (row & 7);
            uint32_t off = (uint32_t)((row * CH + ((gg ^ swz) << 2)) * 4);
            int gk = k0 + gg * 4;
            cp16(sb + off,                   Ahi + (size_t)(m0 + row) * K + gk);
            cp16(sb + (uint32_t)T * 4 + off, Bhi + (size_t)(n0 + row) * K + gk);
            if (TERMS >= 2)
                cp16(sb + 2u * T * 4 + off, Blo + (size_t)(n0 + row) * K + gk);
            if (TERMS == 3)
                cp16(sb + 3u * T * 4 + off, Alo + (size_t)(m0 + row) * K + gk);
        }
        asm volatile("cp.async.commit_group;" ::: "memory");
    };

    issue(0);
    issue(1);

    for (int c = 0; c < NC; c++) {
        asm volatile("cp.async.wait_group %0;" :: "n"(STAGES - 2));
        __syncthreads();
        if (c + STAGES - 1 < NC) issue(c + STAGES - 1);

        const uint32_t stb = smb + (uint32_t)((c % STAGES) * SS * 4);
        uint32_t aAh[4], aAl[4], aBh[2], aBl[2];
#pragma unroll
        for (int mt = 0; mt < 4; mt++) {
            int row = wm * 64 + mt * 16 + ao;
            aAh[mt] = stb + (uint32_t)(row * CH * 4);
            if (TERMS == 3) aAl[mt] = aAh[mt] + 3u * T * 4;
        }
#pragma unroll
        for (int ntp = 0; ntp < 2; ntp++) {
            int row = wn * 32 + ntp * 16 + bo;
            aBh[ntp] = stb + (uint32_t)(T * 4 + row * CH * 4);
            if (TERMS >= 2) aBl[ntp] = aBh[ntp] + (uint32_t)(T * 4);
        }

#pragma unroll
        for (int ks = 0; ks < CH / 8; ks++) {
            const uint32_t offA = (uint32_t)(((2 * ks + ak) ^ swzA) << 4);
            const uint32_t offB = (uint32_t)(((2 * ks + bk) ^ swzB) << 4);
            uint32_t afh[4][4], afl[4][4], bfh[4][2], bfl[4][2];
#pragma unroll
            for (int mt = 0; mt < 4; mt++) {
                LDSM4(afh[mt][0], afh[mt][1], afh[mt][2], afh[mt][3], aAh[mt] + offA);
                if (TERMS == 3)
                    LDSM4(afl[mt][0], afl[mt][1], afl[mt][2], afl[mt][3], aAl[mt] + offA);
            }
            LDSM4(bfh[0][0], bfh[0][1], bfh[1][0], bfh[1][1], aBh[0] + offB);
            LDSM4(bfh[2][0], bfh[2][1], bfh[3][0], bfh[3][1], aBh[1] + offB);
            if (TERMS >= 2) {
                LDSM4(bfl[0][0], bfl[0][1], bfl[1][0], bfl[1][1], aBl[0] + offB);
                LDSM4(bfl[2][0], bfl[2][1], bfl[3][0], bfl[3][1], aBl[1] + offB);
            }
#pragma unroll
            for (int mt = 0; mt < 4; mt++)
#pragma unroll
                for (int nt = 0; nt < 4; nt++) {
                    float* a = acc[mt][nt];
                    mma_tf32(a[0], a[1], a[2], a[3],
                             afh[mt][0], afh[mt][1], afh[mt][2], afh[mt][3],
                             bfh[nt][0], bfh[nt][1]);
                    if (TERMS >= 2)
                        mma_tf32(a[0], a[1], a[2], a[3],
                                 afh[mt][0], afh[mt][1], afh[mt][2], afh[mt][3],
                                 bfl[nt][0], bfl[nt][1]);
                    if (TERMS == 3)
                        mma_tf32(a[0], a[1], a[2], a[3],
                                 afl[mt][0], afl[mt][1], afl[mt][2], afl[mt][3],
                                 bfh[nt][0], bfh[nt][1]);
                }
        }
    }

#pragma unroll
    for (int mt = 0; mt < 4; mt++) {
#pragma unroll
        for (int nt = 0; nt < 4; nt++) {
            int row = m0 + wm * 64 + mt * 16 + g;
            int col = n0 + wn * 32 + nt * 8 + ct * 2;
            float v0 = acc[mt][nt][0], v1 = acc[mt][nt][1];
            float v2 = acc[mt][nt][2], v3 = acc[mt][nt][3];
            if (bias) {
                float b0 = bias[col], b1 = bias[col + 1];
                v0 += b0; v1 += b1; v2 += b0; v3 += b1;
            }
            if (do_clip) {
                v0 = fminf(fmaxf(v0, -10.f), 10.f);
                v1 = fminf(fmaxf(v1, -10.f), 10.f);
                v2 = fminf(fmaxf(v2, -10.f), 10.f);
                v3 = fminf(fmaxf(v3, -10.f), 10.f);
            }
            float2 lo2; lo2.x = v0; lo2.y = v1;
            float2 hi2; hi2.x = v2; hi2.y = v3;
            *(float2*)(C + (size_t)row * ldc + col) = lo2;
            *(float2*)(C + (size_t)(row + 8) * ldc + col) = hi2;
        }
    }

    if (scores2) {
        const int head = (n0 >> 6) + (wn >> 1);
        const int slot = wn & 1;
#pragma unroll
        for (int mt = 0; mt < 4; mt++) {
#pragma unroll
            for (int hf = 0; hf < 2; hf++) {
                float s = 0.f;
#pragma unroll
                for (int nt = 0; nt < 4; nt++) {
                    float a = acc[mt][nt][hf * 2 + 0];
                    float b = acc[mt][nt][hf * 2 + 1];
                    s += a * a + b * b;
                }
                s += __shfl_xor_sync(0xffffffffu, s, 1);
                s += __shfl_xor_sync(0xffffffffu, s, 2);
                if (ct == 0) {
                    int row = m0 + wm * 64 + mt * 16 + g + hf * 8;
                    scores2[((size_t)row * NH + head) * 2 + slot] = s;
                }
            }
        }
    }
}

// q only: [8192 x 768], 3-term tf32 (top-k safe) + fused score partials
__global__ __launch_bounds__(256, 2) void q_gemm(
    const float* __restrict__ xhi, const float* __restrict__ xlo,
    const float* __restrict__ wTh, const float* __restrict__ wTl,
    float* __restrict__ C, float* __restrict__ scores2)
{
    extern __shared__ float sm[];
    gemm_body<3, 16>(xhi, xlo, wTh, wTl, C, CDIM, CDIM, nullptr, 0, sm, scores2);
}

// proj: 1-term tf32 (A already exact tf32; B-lo dropped, adds ~1.4e-4 rel rms)
__global__ __launch_bounds__(256, 2) void proj_gemm(
    const float* __restrict__ A, const float* __restrict__ Bh,
    const float* __restrict__ bias, float* __restrict__ C)
{
    extern __shared__ float sm[];
    gemm_body<1, 16>(A, nullptr, Bh, nullptr, C, CDIM, CDIM, bias, 1, sm, nullptr);
}

// ============================================================================
// Gather-GEMM: per (b,h) compute Ksel = x[keep]·w_k[h], Vsel = x[keep]·w_v[h].
// ============================================================================
__global__ __launch_bounds__(256, 2) void kvg_gemm(
    const float* __restrict__ xhi, const float* __restrict__ wTh,
    const int* __restrict__ keep,
    float* __restrict__ ksel, float* __restrict__ vselT)
{
    extern __shared__ float sm[];
    constexpr int CH = 32, STAGES = 3;
    constexpr int T  = 128 * CH;
    constexpr int SS = 2 * T;

    const int tid = threadIdx.x, lane = tid & 31, wid = tid >> 5;
    const int g = lane >> 2, ct = lane & 3;
    const int wm = wid & 1, wn = wid >> 1;
    const int m0 = blockIdx.x * 128;
    const int bh = blockIdx.y, b = bh / NH, h = bh % NH;

    const int ao = ((lane >> 3) & 1) * 8 + (lane & 7);
    const int ak = lane >> 4;
    const int bo = (lane >> 4) * 8 + (lane & 7);
    const int bk = (lane >> 3) & 1;
    const int swzA = ao & 7;
    const int swzB = bo & 7;

    const int lrow = tid >> 3, lgg = tid & 7;
    const float* aptr[4];
    const float* bptr[4];
    uint32_t soff[4];
#pragma unroll
    for (int j = 0; j < 4; j++) {
        int row = lrow + 32 * j;
        int tok = keep[bh * KEEP + m0 + row];
        aptr[j] = xhi + (size_t)(b * NTOK + tok) * CDIM + lgg * 4;
        int wrow = (row < 64) ? (CDIM + h * HD + row) : (2 * CDIM + h * HD + row - 64);
        bptr[j] = wTh + (size_t)wrow * CDIM + lgg * 4;
        soff[j] = (uint32_t)((row * CH + ((lgg ^ (row & 7)) << 2)) * 4);
    }

    float acc[4][4][4];
#pragma unroll
    for (int mt = 0; mt < 4; mt++)
#pragma unroll
        for (int nt = 0; nt < 4; nt++)
#pragma unroll
            for (int i = 0; i < 4; i++) acc[mt][nt][i] = 0.f;

    const uint32_t smb = smem_u32(sm);
    const int NC = CDIM / CH;

    auto issue = [&](int c) {
        const uint32_t sb = smb + (uint32_t)((c % STAGES) * SS * 4);
        const int k0 = c * CH;
#pragma unroll
        for (int j = 0; j < 4; j++) {
            cp16(sb + soff[j],                   aptr[j] + k0);
            cp16(sb + (uint32_t)T * 4 + soff[j], bptr[j] + k0);
        }
        asm volatile("cp.async.commit_group;" ::: "memory");
    };

    issue(0);
    issue(1);

    for (int c = 0; c < NC; c++) {
        asm volatile("cp.async.wait_group %0;" :: "n"(STAGES - 2));
        __syncthreads();
        if (c + STAGES - 1 < NC) issue(c + STAGES - 1);

        const uint32_t stb = smb + (uint32_t)((c % STAGES) * SS * 4);
        uint32_t aA[4], aB[2];
#pragma unroll
        for (int mt = 0; mt < 4; mt++)
            aA[mt] = stb + (uint32_t)((wm * 64 + mt * 16 + ao) * CH * 4);
#pragma unroll
        for (int ntp = 0; ntp < 2; ntp++)
            aB[ntp] = stb + (uint32_t)(T * 4 + (wn * 32 + ntp * 16 + bo) * CH * 4);

#pragma unroll
        for (int ks = 0; ks < CH / 8; ks++) {
            const uint32_t offA = (uint32_t)(((2 * ks + ak) ^ swzA) << 4);
            const uint32_t offB = (uint32_t)(((2 * ks + bk) ^ swzB) << 4);
            uint32_t af[4][4], bf[4][2];
#pragma unroll
            for (int mt = 0; mt < 4; mt++)
                LDSM4(af[mt][0], af[mt][1], af[mt][2], af[mt][3], aA[mt] + offA);
            LDSM4(bf[0][0], bf[0][1], bf[1][0], bf[1][1], aB[0] + offB);
            LDSM4(bf[2][0], bf[2][1], bf[3][0], bf[3][1], aB[1] + offB);
#pragma unroll
            for (int mt = 0; mt < 4; mt++)
#pragma unroll
                for (int nt = 0; nt < 4; nt++)
                    mma_tf32(acc[mt][nt][0], acc[mt][nt][1], acc[mt][nt][2], acc[mt][nt][3],
                             af[mt][0], af[mt][1], af[mt][2], af[mt][3],
                             bf[nt][0], bf[nt][1]);
        }
    }

    __syncthreads();

    if (wn < 2) {
#pragma unroll
        for (int mt = 0; mt < 4; mt++) {
#pragma unroll
            for (int nt = 0; nt < 4; nt++) {
                int j0 = wm * 64 + mt * 16 + g;
                int d  = wn * 32 + nt * 8 + ct * 2;
                float2 a;
                a.x = tf32_rna(acc[mt][nt][0]); a.y = tf32_rna(acc[mt][nt][1]);
                *(float2*)(ksel + ((size_t)bh * KEEP + m0 + j0) * HD + d) = a;
                float2 c2;
                c2.x = tf32_rna(acc[mt][nt][2]); c2.y = tf32_rna(acc[mt][nt][3]);
                *(float2*)(ksel + ((size_t)bh * KEEP + m0 + j0 + 8) * HD + d) = c2;
            }
        }
    } else {
        float* vst = sm;   // [64][132]
#pragma unroll
        for (int mt = 0; mt < 4; mt++) {
#pragma unroll
            for (int nt = 0; nt < 4; nt++) {
                int j0 = wm * 64 + mt * 16 + g;
                int j1 = j0 + 8;
                int d  = (wn - 2) * 32 + nt * 8 + ct * 2;
                int s0 = (j0 & ~7) | ((j0 & 1) << 2) | ((j0 & 7) >> 1);
                int s1 = (j1 & ~7) | ((j1 & 1) << 2) | ((j1 & 7) >> 1);
                vst[d * 132 + s0]       = tf32_rna(acc[mt][nt][0]);
                vst[(d + 1) * 132 + s0] = tf32_rna(acc[mt][nt][1]);
                vst[d * 132 + s1]       = tf32_rna(acc[mt][nt][2]);
                vst[(d + 1) * 132 + s1] = tf32_rna(acc[mt][nt][3]);
            }
        }
    }
    __syncthreads();

    for (int i = tid; i < 64 * 32; i += 256) {
        int d = i >> 5, f = (i & 31) * 4;
        float4 v;
        v.x = sm[d * 132 + f];     v.y = sm[d * 132 + f + 1];
        v.z = sm[d * 132 + f + 2]; v.w = sm[d * 132 + f + 3];
        *(float4*)(vselT + ((size_t)bh * HD + d) * KEEP + m0 + f) = v;
    }
}

// ============================================================================
// prep: x -> (hi,lo) split  AND  both weight transposes+splits, one launch.
// blocks [0, XB): xsplit; blocks [XB, XB+2304): wsplit (decode 96 x 24).
// ============================================================================
#define XB (ROWS * CDIM / 4 / 256)   /* 6144 */
__global__ void prep_kernel(
    const float* __restrict__ x, float* __restrict__ xhi, float* __restrict__ xlo,
    const float* __restrict__ wq, float* __restrict__ wqh, float* __restrict__ wql,
    const float* __restrict__ wp, float* __restrict__ wph, float* __restrict__ wpl)
{
    __shared__ float t[32][33];
    const int tid = threadIdx.x;
    if (blockIdx.x < XB) {
        int i = blockIdx.x * 256 + tid;
        float4 v = ((const float4*)x)[i];
        float4 h, l;
        h.x = tf32_rna(v.x); l.x = tf32_rna(v.x - h.x);
        h.y = tf32_rna(v.y); l.y = tf32_rna(v.y - h.y);
        h.z = tf32_rna(v.z); l.z = tf32_rna(v.z - h.z);
        h.w = tf32_rna(v.w); l.w = tf32_rna(v.w - h.w);
        ((float4*)xhi)[i] = h;
        ((float4*)xlo)[i] = l;
        return;
    }
    const int bx = blockIdx.x - XB;
    const int nb = bx % 96, kb = bx / 96;
    const float* in; float *ohi, *olo; int n0;
    int N;
    if (nb < C3 / 32) { in = wq; ohi = wqh; olo = wql; n0 = nb * 32; N = C3; }
    else              { in = wp; ohi = wph; olo = wpl; n0 = (nb - C3 / 32) * 32; N = CDIM; }
    const int k0 = kb * 32;
    const int tx = tid & 31, ty = tid >> 5;
#pragma unroll
    for (int i = 0; i < 4; i++)
        t[ty + i * 8][tx] = in[(size_t)(k0 + ty + i * 8) * N + n0 + tx];
    __syncthreads();
#pragma unroll
    for (int i = 0; i < 4; i++) {
        float v = t[tx][ty + i * 8];
        float h = tf32_rna(v);
        ohi[(size_t)(n0 + ty + i * 8) * CDIM + k0 + tx] = h;
        olo[(size_t)(n0 + ty + i * 8) * CDIM + k0 + tx] = tf32_rna(v - h);
    }
}

// ============================================================================
// Per-(b,h) top-KEEP from fused score partials. Bitonic SET selection:
// standard network to k=1024 leaves half A asc / half B desc; top-1024 set =
// elementwise max(keys[i], keys[i+1024]).
// ============================================================================
__global__ __launch_bounds__(1024) void topk_kernel(
    const float* __restrict__ scores2, int* __restrict__ keep)
{
    __shared__ unsigned long long keys[NTOK];
    const int bh = blockIdx.x, t = threadIdx.x;
    const int h = bh % NH, b = bh / NH;
    for (int i = t; i < NTOK; i += 1024) {
        size_t base = ((size_t)(b * NTOK + i) * NH + h) * 2;
        float s = scores2[base] + scores2[base + 1];
        keys[i] = ((unsigned long long)__float_as_uint(s) << 32) | (unsigned)(NTOK - 1 - i);
    }
    for (int k = 2; k <= 1024; k <<= 1) {
        for (int j = k >> 1; j > 0; j >>= 1) {
            __syncthreads();
            for (int i = t; i < NTOK; i += 1024) {
                int ixj = i ^ j;
                if (ixj > i) {
                    unsigned long long a = keys[i], c = keys[ixj];
                    bool asc = ((i & k) == 0);
                    if ((a > c) == asc) { keys[i] = c; keys[ixj] = a; }
                }
            }
        }
    }
    __syncthreads();
    {
        unsigned long long a = keys[t], c = keys[t + 1024];
        unsigned long long mx = (a > c) ? a : c;
        keep[bh * KEEP + t] = (NTOK - 1) - (int)(mx & 0xffffffffu);
    }
}

// ============================================================================
// mma.sync attention (proven config): warp-row-split + 2-stage cp.async,
// key chunks of 64, P in registers, V pre-permuted. smem 96KB, 2 CTAs/SM.
// ============================================================================
__global__ __launch_bounds__(256, 2) void attn_mma(
    const float* __restrict__ q, const float* __restrict__ ksel,
    const float* __restrict__ vselT, float* __restrict__ out)
{
    extern __shared__ float sm[];
    float* Qs = sm;
    const uint32_t smb    = smem_u32(sm);
    const uint32_t stage0 = smb + 8192u * 4;

    const int tid = threadIdx.x, lane = tid & 31, wid = tid >> 5;
    const int g = lane >> 2, ct = lane & 3;
    const int bh = blockIdx.y, b = bh / NH, h = bh % NH;
    const int qbase = blockIdx.x * 128;

    const int ao = ((lane >> 3) & 1) * 8 + (lane & 7);
    const int ak = lane >> 4;
    const int bo = (lane >> 4) * 8 + (lane & 7);
    const int bk = (lane >> 3) & 1;
    const int swzq = ao & 7;
    const int swzb = bo & 7;

    {
        int j = tid & 127, half = tid >> 7;
        const float* qrow = q + (size_t)(b * NTOK + qbase + j) * CDIM + h * HD + half * 32;
        const float QSC = 0.125f * 1.44269504f;
#pragma unroll
        for (int i = 0; i < 8; i++) {
            float4 v = *(const float4*)(qrow + i * 4);
            v.x = tf32_rna(v.x * QSC); v.y = tf32_rna(v.y * QSC);
            v.z = tf32_rna(v.z * QSC); v.w = tf32_rna(v.w * QSC);
            int c = half * 32 + i * 4;
            *(float4*)&Qs[j * 64 + (c ^ ((j & 7) << 2))] = v;
        }
    }

    const float* kbase = ksel  + (size_t)bh * KEEP * HD;
    const float* vbase = vselT + (size_t)bh * HD * KEEP;

    auto issue = [&](int kc) {
        const uint32_t sb = stage0 + (uint32_t)((kc & 1) * 8192 * 4);
#pragma unroll
        for (int j = 0; j < 4; j++) {
            int gidx = tid + j * 256;
            int row = gidx >> 4, gg = gidx & 15;
            uint32_t off = (uint32_t)((row * 64 + ((gg ^ (row & 7)) << 2)) * 4);
            cp16(sb + off, kbase + (size_t)(kc * 64 + row) * HD + gg * 4);
            cp16(sb + 4096u * 4 + off, vbase + (size_t)row * KEEP + kc * 64 + gg * 4);
        }
        asm volatile("cp.async.commit_group;" ::: "memory");
    };

    const uint32_t qa_base = smb + (uint32_t)((wid * 16 + ao) * 64 * 4);

    float P[8][4];
    float O[8][4];
    float lp0 = 0.f, lp1 = 0.f;
#pragma unroll
    for (int dt = 0; dt < 8; dt++)
#pragma unroll
        for (int i = 0; i < 4; i++) O[dt][i] = 0.f;

    issue(0);

    for (int kc = 0; kc < KEEP / 64; kc++) {
        if (kc + 1 < KEEP / 64) {
            issue(kc + 1);
            asm volatile("cp.async.wait_group 1;" ::: "memory");
        } else {
            asm volatile("cp.async.wait_group 0;" ::: "memory");
        }
        __syncthreads();

        const uint32_t kst = stage0 + (uint32_t)((kc & 1) * 8192 * 4);
        const uint32_t vst = kst + 4096u * 4;

#pragma unroll
        for (int nt = 0; nt < 8; nt++)
#pragma unroll
            for (int i = 0; i < 4; i++) P[nt][i] = 0.f;

#pragma unroll
        for (int ks = 0; ks < 8; ks++) {
            const uint32_t offq = (uint32_t)(((2 * ks + ak) ^ swzq) << 4);
            const uint32_t offb = (uint32_t)(((2 * ks + bk) ^ swzb) << 4);
            uint32_t qa0, qa1, qa2, qa3;
            LDSM4(qa0, qa1, qa2, qa3, qa_base + offq);
#pragma unroll
            for (int ntp = 0; ntp < 4; ntp++) {
                uint32_t k00, k01, k10, k11;
                LDSM4(k00, k01, k10, k11, kst + (uint32_t)((ntp * 16 + bo) * 64 * 4) + offb);
                mma_tf32(P[2 * ntp][0], P[2 * ntp][1], P[2 * ntp][2], P[2 * ntp][3],
                         qa0, qa1, qa2, qa3, k00, k01);
                mma_tf32(P[2 * ntp + 1][0], P[2 * ntp + 1][1], P[2 * ntp + 1][2], P[2 * ntp + 1][3],
                         qa0, qa1, qa2, qa3, k10, k11);
            }
        }

#pragma unroll
        for (int nt = 0; nt < 8; nt++) {
            float p0 = pexp(P[nt][0]);
            float p1 = pexp(P[nt][1]);
            float p2 = pexp(P[nt][2]);
            float p3 = pexp(P[nt][3]);
            lp0 += p0 + p1;
            lp1 += p2 + p3;
            P[nt][0] = p0; P[nt][1] = p1; P[nt][2] = p2; P[nt][3] = p3;
        }

#pragma unroll
        for (int ks = 0; ks < 8; ks++) {
            const uint32_t offv = (uint32_t)(((2 * ks + bk) ^ swzb) << 4);
            uint32_t a0 = __float_as_uint(P[ks][0]);
            uint32_t a1 = __float_as_uint(P[ks][2]);
            uint32_t a2 = __float_as_uint(P[ks][1]);
            uint32_t a3 = __float_as_uint(P[ks][3]);
#pragma unroll
            for (int dtp = 0; dtp < 4; dtp++) {
                uint32_t v00, v01, v10, v11;
                LDSM4(v00, v01, v10, v11, vst + (uint32_t)((dtp * 16 + bo) * 64 * 4) + offv);
                mma_tf32(O[2 * dtp][0], O[2 * dtp][1], O[2 * dtp][2], O[2 * dtp][3],
                         a0, a1, a2, a3, v00, v01);
                mma_tf32(O[2 * dtp + 1][0], O[2 * dtp + 1][1], O[2 * dtp + 1][2], O[2 * dtp + 1][3],
                         a0, a1, a2, a3, v10, v11);
            }
        }
        __syncthreads();
    }

    lp0 += __shfl_xor_sync(0xffffffffu, lp0, 1);
    lp0 += __shfl_xor_sync(0xffffffffu, lp0, 2);
    lp1 += __shfl_xor_sync(0xffffffffu, lp1, 1);
    lp1 += __shfl_xor_sync(0xffffffffu, lp1, 2);
    const float li0 = 1.f / lp0, li1 = 1.f / lp1;

    const int row0 = qbase + wid * 16 + g;
#pragma unroll
    for (int dt = 0; dt < 8; dt++) {
        int d0 = dt * 8 + 2 * ct;
        float2 a;
        a.x = tf32_rna(O[dt][0] * li0);
        a.y = tf32_rna(O[dt][1] * li0);
        *(float2*)&out[(size_t)(b * NTOK + row0) * CDIM + h * HD + d0] = a;
        float2 c;
        c.x = tf32_rna(O[dt][2] * li1);
        c.y = tf32_rna(O[dt][3] * li1);
        *(float2*)&out[(size_t)(b * NTOK + row0 + 8) * CDIM + h * HD + d0] = c;
    }
}

// ============================================================================
// launch
// ============================================================================
extern "C" void kernel_launch(void* const* d_in, const int* in_sizes, int n_in,
                              void* d_out, int out_size)
{
    (void)in_sizes; (void)n_in; (void)out_size;
    const float* x      = (const float*)d_in[0];
    const float* w_qkv  = (const float*)d_in[1];
    const float* w_proj = (const float*)d_in[2];
    const float* b_proj = (const float*)d_in[3];
    float* out = (float*)d_out;

    float *q_p, *sc2_p, *ks_p, *vT_p, *ao_p, *xhi_p, *xlo_p;
    float *wqh_p, *wql_p, *wph_p, *wpl_p;
    int* keep_p;
    cudaGetSymbolAddress((void**)&q_p,    g_q);
    cudaGetSymbolAddress((void**)&sc2_p,  g_scores2);
    cudaGetSymbolAddress((void**)&keep_p, g_keep);
    cudaGetSymbolAddress((void**)&ks_p,   g_ksel);
    cudaGetSymbolAddress((void**)&vT_p,   g_vselT);
    cudaGetSymbolAddress((void**)&ao_p,   g_attnout);
    cudaGetSymbolAddress((void**)&xhi_p,  g_xhi);
    cudaGetSymbolAddress((void**)&xlo_p,  g_xlo);
    cudaGetSymbolAddress((void**)&wqh_p,  g_wqT_hi);
    cudaGetSymbolAddress((void**)&wql_p,  g_wqT_lo);
    cudaGetSymbolAddress((void**)&wph_p,  g_wpT_hi);
    cudaGetSymbolAddress((void**)&wpl_p,  g_wpT_lo);

    const int smem_q    = 3 * 8192 * (int)sizeof(float);   // 98304
    const int smem_proj = 3 * 4096 * (int)sizeof(float);   // 49152 (1-term, 2 tiles)
    const int smem_kvg  = 3 * 8192 * (int)sizeof(float);   // 98304
    cudaFuncSetAttribute(q_gemm,    cudaFuncAttributeMaxDynamicSharedMemorySize, smem_q);
    cudaFuncSetAttribute(proj_gemm, cudaFuncAttributeMaxDynamicSharedMemorySize, smem_proj);
    cudaFuncSetAttribute(kvg_gemm,  cudaFuncAttributeMaxDynamicSharedMemorySize, smem_kvg);
    const int attn_smem = 3 * 8192 * (int)sizeof(float);   // 98304
    cudaFuncSetAttribute(attn_mma, cudaFuncAttributeMaxDynamicSharedMemorySize, attn_smem);

    // 0) prep: x split + both weight transpose/splits, one launch
    prep_kernel<<<XB + 96 * 24, 256>>>(x, xhi_p, xlo_p,
                                       w_qkv, wqh_p, wql_p, w_proj, wph_p, wpl_p);

    // 1) q = x @ w_q  (3-term tf32) + fused score partials
    q_gemm<<<dim3(CDIM / 128, ROWS / 128), 256, smem_q>>>(
        xhi_p, xlo_p, wqh_p, wql_p, q_p, sc2_p);

    // 2) top-k (bitonic set-selection)
    topk_kernel<<<NBH, 1024>>>(sc2_p, keep_p);

    // 3) gather-GEMM: Ksel / Vsel^T for selected tokens only
    kvg_gemm<<<dim3(KEEP / 128, NBH), 256, smem_kvg>>>(
        xhi_p, wqh_p, keep_p, ks_p, vT_p);

    // 4) attention on tensor cores (chunk 64, 2 CTAs/SM)
    attn_mma<<<dim3(NTOK / 128, NBH), 256, attn_smem>>>(q_p, ks_p, vT_p, ao_p);

    // 5) out = clip(attnout @ w_proj + b_proj, -10, 10)  (1-term tf32)
    proj_gemm<<<dim3(CDIM / 128, ROWS / 128), 256, smem_proj>>>(
        ao_p, wph_p, b_proj, out);
}

// round 17
// speedup vs baseline: 1.1975x; 1.0220x over previous
#include <cuda_runtime.h>
#include <math.h>
#include <cstdint>

#define NH    12
#define NTOK  2048
#define BATCH 4
#define CDIM  768
#define HD    64
#define KEEP  1024
#define ROWS  (BATCH*NTOK)   /* 8192 */
#define C3    (3*CDIM)       /* 2304 */
#define NBH   (BATCH*NH)     /* 48 */
#define CLIPV 72.134689f     /* 50 * log2(e) */

// ---- scratch (static device globals; no runtime allocation) ----
__device__ float g_q[(size_t)ROWS * CDIM];          // q only, [row][768]
__device__ float g_scores2[(size_t)ROWS * NH * 2];  // per-(row,head) 2-slot partial sums
__device__ int   g_keep[NBH * KEEP];
__device__ float g_ksel [(size_t)NBH * KEEP * HD];  // [bh][j][d] row-major, tf32
__device__ float g_vselT[(size_t)NBH * HD * KEEP];  // [bh][d][slot] transposed+permuted
__device__ float g_attnout[(size_t)ROWS * CDIM];
__device__ float g_xhi[(size_t)ROWS * CDIM];
__device__ float g_xlo[(size_t)ROWS * CDIM];
__device__ float g_wqT_hi[(size_t)C3 * CDIM];       // w_qkv^T [2304][768]
__device__ float g_wqT_lo[(size_t)C3 * CDIM];
__device__ float g_wpT_hi[(size_t)CDIM * CDIM];
__device__ float g_wpT_lo[(size_t)CDIM * CDIM];

__device__ __forceinline__ float tf32_rna(float a) {
    float r; asm("cvt.rna.tf32.f32 %0, %1;" : "=f"(r) : "f"(a)); return r;
}
__device__ __forceinline__ float pexp(float s) {
    s = fminf(fmaxf(s, -CLIPV), CLIPV);
    float r; asm("ex2.approx.ftz.f32 %0, %1;" : "=f"(r) : "f"(s)); return r;
}
__device__ __forceinline__ uint32_t smem_u32(const void* p) {
    uint32_t a;
    asm("{ .reg .u64 t; cvta.to.shared.u64 t, %1; cvt.u32.u64 %0, t; }" : "=r"(a) : "l"(p));
    return a;
}
__device__ __forceinline__ void cp16(uint32_t dst, const float* src) {
    size_t ga = __cvta_generic_to_global(src);
    asm volatile("cp.async.cg.shared.global [%0], [%1], 16;" :: "r"(dst), "l"(ga));
}
__device__ __forceinline__ void mma_tf32(float& c0, float& c1, float& c2, float& c3,
                                         uint32_t a0, uint32_t a1, uint32_t a2, uint32_t a3,
                                         uint32_t b0, uint32_t b1) {
    asm volatile("mma.sync.aligned.m16n8k8.row.col.f32.tf32.tf32.f32 "
        "{%0,%1,%2,%3}, {%4,%5,%6,%7}, {%8,%9}, {%0,%1,%2,%3};"
        : "+f"(c0), "+f"(c1), "+f"(c2), "+f"(c3)
        : "r"(a0), "r"(a1), "r"(a2), "r"(a3), "r"(b0), "r"(b1));
}
#define LDSM4(r0_, r1_, r2_, r3_, addr_) \
    asm volatile("ldmatrix.sync.aligned.m8n8.x4.shared.b16 {%0,%1,%2,%3}, [%4];" \
        : "=r"(r0_), "=r"(r1_), "=r"(r2_), "=r"(r3_) : "r"(addr_) )

// ============================================================================
// 3-stage cp.async mma.sync tf32 GEMM body (dense), ldmatrix feeds.
// C[M,N] = A[M,K] @ BT[N,K]^T, CTA tile 128x128, 8 warps (2m x 4n).
// TERMS=3: Ah*Bh + Ah*Bl + Al*Bh;  TERMS=2: Ah*(Bh+Bl);  TERMS=1: Ah*Bh.
// scores2 != nullptr: also emit per-(row,head) sum-of-squares partials.
// ============================================================================
template<int TERMS, int CH>
__device__ __forceinline__ void gemm_body(
    const float* __restrict__ Ahi, const float* __restrict__ Alo,
    const float* __restrict__ Bhi, const float* __restrict__ Blo,
    float* __restrict__ C, int K, int ldc,
    const float* __restrict__ bias, int do_clip, float* sm,
    float* __restrict__ scores2)
{
    constexpr int STAGES = 3;
    constexpr int T  = 128 * CH;
    constexpr int NT = (TERMS == 3) ? 4 : (TERMS + 1);
    constexpr int SS = NT * T;
    constexpr int GPR = CH / 4;
    constexpr int GPT = 128 * GPR / 256;

    const int tid = threadIdx.x, lane = tid & 31, wid = tid >> 5;
    const int g = lane >> 2, ct = lane & 3;
    const int wm = wid & 1, wn = wid >> 1;
    const int m0 = blockIdx.y * 128, n0 = blockIdx.x * 128;

    const int ao = ((lane >> 3) & 1) * 8 + (lane & 7);
    const int ak = lane >> 4;
    const int bo = (lane >> 4) * 8 + (lane & 7);
    const int bk = (lane >> 3) & 1;
    const int swzA = (CH == 16) ? ((ao >> 1) & 3) : (ao & 7);
    const int swzB = (CH == 16) ? ((bo >> 1) & 3) : (bo & 7);

    float acc[4][4][4];
#pragma unroll
    for (int mt = 0; mt < 4; mt++)
#pragma unroll
        for (int nt = 0; nt < 4; nt++)
#pragma unroll
            for (int i = 0; i < 4; i++) acc[mt][nt][i] = 0.f;

    const uint32_t smb = smem_u32(sm);
    const int NC = K / CH;

    auto issue = [&](int c) {
        const uint32_t sb = smb + (uint32_t)((c % STAGES) * SS * 4);
        const int k0 = c * CH;
#pragma unroll
        for (int j = 0; j < GPT; j++) {
            int gidx = tid + j * 256;
            int row = gidx / GPR, gg = gidx & (GPR - 1);
            int swz = (CH == 16) ? ((row >> 1) & 3) : (row & 7);
            uint32_t off = (uint32_t)((row * CH + ((gg ^ swz) << 2)) * 4);
            int gk = k0 + gg * 4;
            cp16(sb + off,                   Ahi + (size_t)(m0 + row) * K + gk);
            cp16(sb + (uint32_t)T * 4 + off, Bhi + (size_t)(n0 + row) * K + gk);
            if (TERMS >= 2)
                cp16(sb + 2u * T * 4 + off, Blo + (size_t)(n0 + row) * K + gk);
            if (TERMS == 3)
                cp16(sb + 3u * T * 4 + off, Alo + (size_t)(m0 + row) * K + gk);
        }
        asm volatile("cp.async.commit_group;" ::: "memory");
    };

    issue(0);
    issue(1);

    for (int c = 0; c < NC; c++) {
        asm volatile("cp.async.wait_group %0;" :: "n"(STAGES - 2));
        __syncthreads();
        if (c + STAGES - 1 < NC) issue(c + STAGES - 1);

        const uint32_t stb = smb + (uint32_t)((c % STAGES) * SS * 4);
        uint32_t aAh[4], aAl[4], aBh[2], aBl[2];
#pragma unroll
        for (int mt = 0; mt < 4; mt++) {
            int row = wm * 64 + mt * 16 + ao;
            aAh[mt] = stb + (uint32_t)(row * CH * 4);
            if (TERMS == 3) aAl[mt] = aAh[mt] + 3u * T * 4;
        }
#pragma unroll
        for (int ntp = 0; ntp < 2; ntp++) {
            int row = wn * 32 + ntp * 16 + bo;
            aBh[ntp] = stb + (uint32_t)(T * 4 + row * CH * 4);
            if (TERMS >= 2) aBl[ntp] = aBh[ntp] + (uint32_t)(T * 4);
        }

#pragma unroll
        for (int ks = 0; ks < CH / 8; ks++) {
            const uint32_t offA = (uint32_t)(((2 * ks + ak) ^ swzA) << 4);
            const uint32_t offB = (uint32_t)(((2 * ks + bk) ^ swzB) << 4);
            uint32_t afh[4][4], afl[4][4], bfh[4][2], bfl[4][2];
#pragma unroll
            for (int mt = 0; mt < 4; mt++) {
                LDSM4(afh[mt][0], afh[mt][1], afh[mt][2], afh[mt][3], aAh[mt] + offA);
                if (TERMS == 3)
                    LDSM4(afl[mt][0], afl[mt][1], afl[mt][2], afl[mt][3], aAl[mt] + offA);
            }
            LDSM4(bfh[0][0], bfh[0][1], bfh[1][0], bfh[1][1], aBh[0] + offB);
            LDSM4(bfh[2][0], bfh[2][1], bfh[3][0], bfh[3][1], aBh[1] + offB);
            if (TERMS >= 2) {
                LDSM4(bfl[0][0], bfl[0][1], bfl[1][0], bfl[1][1], aBl[0] + offB);
                LDSM4(bfl[2][0], bfl[2][1], bfl[3][0], bfl[3][1], aBl[1] + offB);
            }
#pragma unroll
            for (int mt = 0; mt < 4; mt++)
#pragma unroll
                for (int nt = 0; nt < 4; nt++) {
                    float* a = acc[mt][nt];
                    mma_tf32(a[0], a[1], a[2], a[3],
                             afh[mt][0], afh[mt][1], afh[mt][2], afh[mt][3],
                             bfh[nt][0], bfh[nt][1]);
                    if (TERMS >= 2)
                        mma_tf32(a[0], a[1], a[2], a[3],
                                 afh[mt][0], afh[mt][1], afh[mt][2], afh[mt][3],
                                 bfl[nt][0], bfl[nt][1]);
                    if (TERMS == 3)
                        mma_tf32(a[0], a[1], a[2], a[3],
                                 afl[mt][0], afl[mt][1], afl[mt][2], afl[mt][3],
                                 bfh[nt][0], bfh[nt][1]);
                }
        }
    }

#pragma unroll
    for (int mt = 0; mt < 4; mt++) {
#pragma unroll
        for (int nt = 0; nt < 4; nt++) {
            int row = m0 + wm * 64 + mt * 16 + g;
            int col = n0 + wn * 32 + nt * 8 + ct * 2;
            float v0 = acc[mt][nt][0], v1 = acc[mt][nt][1];
            float v2 = acc[mt][nt][2], v3 = acc[mt][nt][3];
            if (bias) {
                float b0 = bias[col], b1 = bias[col + 1];
                v0 += b0; v1 += b1; v2 += b0; v3 += b1;
            }
            if (do_clip) {
                v0 = fminf(fmaxf(v0, -10.f), 10.f);
                v1 = fminf(fmaxf(v1, -10.f), 10.f);
                v2 = fminf(fmaxf(v2, -10.f), 10.f);
                v3 = fminf(fmaxf(v3, -10.f), 10.f);
            }
            float2 lo2; lo2.x = v0; lo2.y = v1;
            float2 hi2; hi2.x = v2; hi2.y = v3;
            *(float2*)(C + (size_t)row * ldc + col) = lo2;
            *(float2*)(C + (size_t)(row + 8) * ldc + col) = hi2;
        }
    }

    if (scores2) {
        const int head = (n0 >> 6) + (wn >> 1);
        const int slot = wn & 1;
#pragma unroll
        for (int mt = 0; mt < 4; mt++) {
#pragma unroll
            for (int hf = 0; hf < 2; hf++) {
                float s = 0.f;
#pragma unroll
                for (int nt = 0; nt < 4; nt++) {
                    float a = acc[mt][nt][hf * 2 + 0];
                    float b = acc[mt][nt][hf * 2 + 1];
                    s += a * a + b * b;
                }
                s += __shfl_xor_sync(0xffffffffu, s, 1);
                s += __shfl_xor_sync(0xffffffffu, s, 2);
                if (ct == 0) {
                    int row = m0 + wm * 64 + mt * 16 + g + hf * 8;
                    scores2[((size_t)row * NH + head) * 2 + slot] = s;
                }
            }
        }
    }
}

// q only: [8192 x 768], 3-term tf32 (top-k safe) + fused score partials
__global__ __launch_bounds__(256, 2) void q_gemm(
    const float* __restrict__ xhi, const float* __restrict__ xlo,
    const float* __restrict__ wTh, const float* __restrict__ wTl,
    float* __restrict__ C, float* __restrict__ scores2)
{
    extern __shared__ float sm[];
    gemm_body<3, 16>(xhi, xlo, wTh, wTl, C, CDIM, CDIM, nullptr, 0, sm, scores2);
}

// proj: 1-term tf32, CH=32 (half the barrier rounds of CH=16; bit-identical sum order)
__global__ __launch_bounds__(256, 2) void proj_gemm(
    const float* __restrict__ A, const float* __restrict__ Bh,
    const float* __restrict__ bias, float* __restrict__ C)
{
    extern __shared__ float sm[];
    gemm_body<1, 32>(A, nullptr, Bh, nullptr, C, CDIM, CDIM, bias, 1, sm, nullptr);
}

// ============================================================================
// Gather-GEMM: per (b,h) compute Ksel = x[keep]·w_k[h], Vsel = x[keep]·w_v[h].
// ============================================================================
__global__ __launch_bounds__(256, 2) void kvg_gemm(
    const float* __restrict__ xhi, const float* __restrict__ wTh,
    const int* __restrict__ keep,
    float* __restrict__ ksel, float* __restrict__ vselT)
{
    extern __shared__ float sm[];
    constexpr int CH = 32, STAGES = 3;
    constexpr int T  = 128 * CH;
    constexpr int SS = 2 * T;

    const int tid = threadIdx.x, lane = tid & 31, wid = tid >> 5;
    const int g = lane >> 2, ct = lane & 3;
    const int wm = wid & 1, wn = wid >> 1;
    const int m0 = blockIdx.x * 128;
    const int bh = blockIdx.y, b = bh / NH, h = bh % NH;

    const int ao = ((lane >> 3) & 1) * 8 + (lane & 7);
    const int ak = lane >> 4;
    const int bo = (lane >> 4) * 8 + (lane & 7);
    const int bk = (lane >> 3) & 1;
    const int swzA = ao & 7;
    const int swzB = bo & 7;

    const int lrow = tid >> 3, lgg = tid & 7;
    const float* aptr[4];
    const float* bptr[4];
    uint32_t soff[4];
#pragma unroll
    for (int j = 0; j < 4; j++) {
        int row = lrow + 32 * j;
        int tok = keep[bh * KEEP + m0 + row];
        aptr[j] = xhi + (size_t)(b * NTOK + tok) * CDIM + lgg * 4;
        int wrow = (row < 64) ? (CDIM + h * HD + row) : (2 * CDIM + h * HD + row - 64);
        bptr[j] = wTh + (size_t)wrow * CDIM + lgg * 4;
        soff[j] = (uint32_t)((row * CH + ((lgg ^ (row & 7)) << 2)) * 4);
    }

    float acc[4][4][4];
#pragma unroll
    for (int mt = 0; mt < 4; mt++)
#pragma unroll
        for (int nt = 0; nt < 4; nt++)
#pragma unroll
            for (int i = 0; i < 4; i++) acc[mt][nt][i] = 0.f;

    const uint32_t smb = smem_u32(sm);
    const int NC = CDIM / CH;

    auto issue = [&](int c) {
        const uint32_t sb = smb + (uint32_t)((c % STAGES) * SS * 4);
        const int k0 = c * CH;
#pragma unroll
        for (int j = 0; j < 4; j++) {
            cp16(sb + soff[j],                   aptr[j] + k0);
            cp16(sb + (uint32_t)T * 4 + soff[j], bptr[j] + k0);
        }
        asm volatile("cp.async.commit_group;" ::: "memory");
    };

    issue(0);
    issue(1);

    for (int c = 0; c < NC; c++) {
        asm volatile("cp.async.wait_group %0;" :: "n"(STAGES - 2));
        __syncthreads();
        if (c + STAGES - 1 < NC) issue(c + STAGES - 1);

        const uint32_t stb = smb + (uint32_t)((c % STAGES) * SS * 4);
        uint32_t aA[4], aB[2];
#pragma unroll
        for (int mt = 0; mt < 4; mt++)
            aA[mt] = stb + (uint32_t)((wm * 64 + mt * 16 + ao) * CH * 4);
#pragma unroll
        for (int ntp = 0; ntp < 2; ntp++)
            aB[ntp] = stb + (uint32_t)(T * 4 + (wn * 32 + ntp * 16 + bo) * CH * 4);

#pragma unroll
        for (int ks = 0; ks < CH / 8; ks++) {
            const uint32_t offA = (uint32_t)(((2 * ks + ak) ^ swzA) << 4);
            const uint32_t offB = (uint32_t)(((2 * ks + bk) ^ swzB) << 4);
            uint32_t af[4][4], bf[4][2];
#pragma unroll
            for (int mt = 0; mt < 4; mt++)
                LDSM4(af[mt][0], af[mt][1], af[mt][2], af[mt][3], aA[mt] + offA);
            LDSM4(bf[0][0], bf[0][1], bf[1][0], bf[1][1], aB[0] + offB);
            LDSM4(bf[2][0], bf[2][1], bf[3][0], bf[3][1], aB[1] + offB);
#pragma unroll
            for (int mt = 0; mt < 4; mt++)
#pragma unroll
                for (int nt = 0; nt < 4; nt++)
                    mma_tf32(acc[mt][nt][0], acc[mt][nt][1], acc[mt][nt][2], acc[mt][nt][3],
                             af[mt][0], af[mt][1], af[mt][2], af[mt][3],
                             bf[nt][0], bf[nt][1]);
        }
    }

    __syncthreads();

    if (wn < 2) {
#pragma unroll
        for (int mt = 0; mt < 4; mt++) {
#pragma unroll
            for (int nt = 0; nt < 4; nt++) {
                int j0 = wm * 64 + mt * 16 + g;
                int d  = wn * 32 + nt * 8 + ct * 2;
                float2 a;
                a.x = tf32_rna(acc[mt][nt][0]); a.y = tf32_rna(acc[mt][nt][1]);
                *(float2*)(ksel + ((size_t)bh * KEEP + m0 + j0) * HD + d) = a;
                float2 c2;
                c2.x = tf32_rna(acc[mt][nt][2]); c2.y = tf32_rna(acc[mt][nt][3]);
                *(float2*)(ksel + ((size_t)bh * KEEP + m0 + j0 + 8) * HD + d) = c2;
            }
        }
    } else {
        float* vst = sm;   // [64][132]
#pragma unroll
        for (int mt = 0; mt < 4; mt++) {
#pragma unroll
            for (int nt = 0; nt < 4; nt++) {
                int j0 = wm * 64 + mt * 16 + g;
                int j1 = j0 + 8;
                int d  = (wn - 2) * 32 + nt * 8 + ct * 2;
                int s0 = (j0 & ~7) | ((j0 & 1) << 2) | ((j0 & 7) >> 1);
                int s1 = (j1 & ~7) | ((j1 & 1) << 2) | ((j1 & 7) >> 1);
                vst[d * 132 + s0]       = tf32_rna(acc[mt][nt][0]);
                vst[(d + 1) * 132 + s0] = tf32_rna(acc[mt][nt][1]);
                vst[d * 132 + s1]       = tf32_rna(acc[mt][nt][2]);
                vst[(d + 1) * 132 + s1] = tf32_rna(acc[mt][nt][3]);
            }
        }
    }
    __syncthreads();

    for (int i = tid; i < 64 * 32; i += 256) {
        int d = i >> 5, f = (i & 31) * 4;
        float4 v;
        v.x = sm[d * 132 + f];     v.y = sm[d * 132 + f + 1];
        v.z = sm[d * 132 + f + 2]; v.w = sm[d * 132 + f + 3];
        *(float4*)(vselT + ((size_t)bh * HD + d) * KEEP + m0 + f) = v;
    }
}

// ============================================================================
// prep: x -> (hi,lo) split  AND  both weight transposes+splits, one launch.
// ============================================================================
#define XB (ROWS * CDIM / 4 / 256)   /* 6144 */
__global__ void prep_kernel(
    const float* __restrict__ x, float* __restrict__ xhi, float* __restrict__ xlo,
    const float* __restrict__ wq, float* __restrict__ wqh, float* __restrict__ wql,
    const float* __restrict__ wp, float* __restrict__ wph, float* __restrict__ wpl)
{
    __shared__ float t[32][33];
    const int tid = threadIdx.x;
    if (blockIdx.x < XB) {
        int i = blockIdx.x * 256 + tid;
        float4 v = ((const float4*)x)[i];
        float4 h, l;
        h.x = tf32_rna(v.x); l.x = tf32_rna(v.x - h.x);
        h.y = tf32_rna(v.y); l.y = tf32_rna(v.y - h.y);
        h.z = tf32_rna(v.z); l.z = tf32_rna(v.z - h.z);
        h.w = tf32_rna(v.w); l.w = tf32_rna(v.w - h.w);
        ((float4*)xhi)[i] = h;
        ((float4*)xlo)[i] = l;
        return;
    }
    const int bx = blockIdx.x - XB;
    const int nb = bx % 96, kb = bx / 96;
    const float* in; float *ohi, *olo; int n0;
    int N;
    if (nb < C3 / 32) { in = wq; ohi = wqh; olo = wql; n0 = nb * 32; N = C3; }
    else              { in = wp; ohi = wph; olo = wpl; n0 = (nb - C3 / 32) * 32; N = CDIM; }
    const int k0 = kb * 32;
    const int tx = tid & 31, ty = tid >> 5;
#pragma unroll
    for (int i = 0; i < 4; i++)
        t[ty + i * 8][tx] = in[(size_t)(k0 + ty + i * 8) * N + n0 + tx];
    __syncthreads();
#pragma unroll
    for (int i = 0; i < 4; i++) {
        float v = t[tx][ty + i * 8];
        float h = tf32_rna(v);
        ohi[(size_t)(n0 + ty + i * 8) * CDIM + k0 + tx] = h;
        olo[(size_t)(n0 + ty + i * 8) * CDIM + k0 + tx] = tf32_rna(v - h);
    }
}

// ============================================================================
// Per-(b,h) top-KEEP: bitonic network to k=1024 (half A asc / half B desc),
// then top-1024 set = elementwise max(keys[i], keys[i+1024]).
// ============================================================================
__global__ __launch_bounds__(1024) void topk_kernel(
    const float* __restrict__ scores2, int* __restrict__ keep)
{
    __shared__ unsigned long long keys[NTOK];
    const int bh = blockIdx.x, t = threadIdx.x;
    const int h = bh % NH, b = bh / NH;
    for (int i = t; i < NTOK; i += 1024) {
        size_t base = ((size_t)(b * NTOK + i) * NH + h) * 2;
        float s = scores2[base] + scores2[base + 1];
        keys[i] = ((unsigned long long)__float_as_uint(s) << 32) | (unsigned)(NTOK - 1 - i);
    }
    for (int k = 2; k <= 1024; k <<= 1) {
        for (int j = k >> 1; j > 0; j >>= 1) {
            __syncthreads();
            for (int i = t; i < NTOK; i += 1024) {
                int ixj = i ^ j;
                if (ixj > i) {
                    unsigned long long a = keys[i], c = keys[ixj];
                    bool asc = ((i & k) == 0);
                    if ((a > c) == asc) { keys[i] = c; keys[ixj] = a; }
                }
            }
        }
    }
    __syncthreads();
    {
        unsigned long long a = keys[t], c = keys[t + 1024];
        unsigned long long mx = (a > c) ? a : c;
        keep[bh * KEEP + t] = (NTOK - 1) - (int)(mx & 0xffffffffu);
    }
}

// ============================================================================
// mma.sync attention (proven config): warp-row-split + 2-stage cp.async,
// key chunks of 64, P in registers, V pre-permuted. smem 96KB, 2 CTAs/SM.
// ============================================================================
__global__ __launch_bounds__(256, 2) void attn_mma(
    const float* __restrict__ q, const float* __restrict__ ksel,
    const float* __restrict__ vselT, float* __restrict__ out)
{
    extern __shared__ float sm[];
    float* Qs = sm;
    const uint32_t smb    = smem_u32(sm);
    const uint32_t stage0 = smb + 8192u * 4;

    const int tid = threadIdx.x, lane = tid & 31, wid = tid >> 5;
    const int g = lane >> 2, ct = lane & 3;
    const int bh = blockIdx.y, b = bh / NH, h = bh % NH;
    const int qbase = blockIdx.x * 128;

    const int ao = ((lane >> 3) & 1) * 8 + (lane & 7);
    const int ak = lane >> 4;
    const int bo = (lane >> 4) * 8 + (lane & 7);
    const int bk = (lane >> 3) & 1;
    const int swzq = ao & 7;
    const int swzb = bo & 7;

    {
        int j = tid & 127, half = tid >> 7;
        const float* qrow = q + (size_t)(b * NTOK + qbase + j) * CDIM + h * HD + half * 32;
        const float QSC = 0.125f * 1.44269504f;
#pragma unroll
        for (int i = 0; i < 8; i++) {
            float4 v = *(const float4*)(qrow + i * 4);
            v.x = tf32_rna(v.x * QSC); v.y = tf32_rna(v.y * QSC);
            v.z = tf32_rna(v.z * QSC); v.w = tf32_rna(v.w * QSC);
            int c = half * 32 + i * 4;
            *(float4*)&Qs[j * 64 + (c ^ ((j & 7) << 2))] = v;
        }
    }

    const float* kbase = ksel  + (size_t)bh * KEEP * HD;
    const float* vbase = vselT + (size_t)bh * HD * KEEP;

    auto issue = [&](int kc) {
        const uint32_t sb = stage0 + (uint32_t)((kc & 1) * 8192 * 4);
#pragma unroll
        for (int j = 0; j < 4; j++) {
            int gidx = tid + j * 256;
            int row = gidx >> 4, gg = gidx & 15;
            uint32_t off = (uint32_t)((row * 64 + ((gg ^ (row & 7)) << 2)) * 4);
            cp16(sb + off, kbase + (size_t)(kc * 64 + row) * HD + gg * 4);
            cp16(sb + 4096u * 4 + off, vbase + (size_t)row * KEEP + kc * 64 + gg * 4);
        }
        asm volatile("cp.async.commit_group;" ::: "memory");
    };

    const uint32_t qa_base = smb + (uint32_t)((wid * 16 + ao) * 64 * 4);

    float P[8][4];
    float O[8][4];
    float lp0 = 0.f, lp1 = 0.f;
#pragma unroll
    for (int dt = 0; dt < 8; dt++)
#pragma unroll
        for (int i = 0; i < 4; i++) O[dt][i] = 0.f;

    issue(0);

    for (int kc = 0; kc < KEEP / 64; kc++) {
        if (kc + 1 < KEEP / 64) {
            issue(kc + 1);
            asm volatile("cp.async.wait_group 1;" ::: "memory");
        } else {
            asm volatile("cp.async.wait_group 0;" ::: "memory");
        }
        __syncthreads();

        const uint32_t kst = stage0 + (uint32_t)((kc & 1) * 8192 * 4);
        const uint32_t vst = kst + 4096u * 4;

#pragma unroll
        for (int nt = 0; nt < 8; nt++)
#pragma unroll
            for (int i = 0; i < 4; i++) P[nt][i] = 0.f;

#pragma unroll
        for (int ks = 0; ks < 8; ks++) {
            const uint32_t offq = (uint32_t)(((2 * ks + ak) ^ swzq) << 4);
            const uint32_t offb = (uint32_t)(((2 * ks + bk) ^ swzb) << 4);
            uint32_t qa0, qa1, qa2, qa3;
            LDSM4(qa0, qa1, qa2, qa3, qa_base + offq);
#pragma unroll
            for (int ntp = 0; ntp < 4; ntp++) {
                uint32_t k00, k01, k10, k11;
                LDSM4(k00, k01, k10, k11, kst + (uint32_t)((ntp * 16 + bo) * 64 * 4) + offb);
                mma_tf32(P[2 * ntp][0], P[2 * ntp][1], P[2 * ntp][2], P[2 * ntp][3],
                         qa0, qa1, qa2, qa3, k00, k01);
                mma_tf32(P[2 * ntp + 1][0], P[2 * ntp + 1][1], P[2 * ntp + 1][2], P[2 * ntp + 1][3],
                         qa0, qa1, qa2, qa3, k10, k11);
            }
        }

#pragma unroll
        for (int nt = 0; nt < 8; nt++) {
            float p0 = pexp(P[nt][0]);
            float p1 = pexp(P[nt][1]);
            float p2 = pexp(P[nt][2]);
            float p3 = pexp(P[nt][3]);
            lp0 += p0 + p1;
            lp1 += p2 + p3;
            P[nt][0] = p0; P[nt][1] = p1; P[nt][2] = p2; P[nt][3] = p3;
        }

#pragma unroll
        for (int ks = 0; ks < 8; ks++) {
            const uint32_t offv = (uint32_t)(((2 * ks + bk) ^ swzb) << 4);
            uint32_t a0 = __float_as_uint(P[ks][0]);
            uint32_t a1 = __float_as_uint(P[ks][2]);
            uint32_t a2 = __float_as_uint(P[ks][1]);
            uint32_t a3 = __float_as_uint(P[ks][3]);
#pragma unroll
            for (int dtp = 0; dtp < 4; dtp++) {
                uint32_t v00, v01, v10, v11;
                LDSM4(v00, v01, v10, v11, vst + (uint32_t)((dtp * 16 + bo) * 64 * 4) + offv);
                mma_tf32(O[2 * dtp][0], O[2 * dtp][1], O[2 * dtp][2], O[2 * dtp][3],
                         a0, a1, a2, a3, v00, v01);
                mma_tf32(O[2 * dtp + 1][0], O[2 * dtp + 1][1], O[2 * dtp + 1][2], O[2 * dtp + 1][3],
                         a0, a1, a2, a3, v10, v11);
            }
        }
        __syncthreads();
    }

    lp0 += __shfl_xor_sync(0xffffffffu, lp0, 1);
    lp0 += __shfl_xor_sync(0xffffffffu, lp0, 2);
    lp1 += __shfl_xor_sync(0xffffffffu, lp1, 1);
    lp1 += __shfl_xor_sync(0xffffffffu, lp1, 2);
    const float li0 = 1.f / lp0, li1 = 1.f / lp1;

    const int row0 = qbase + wid * 16 + g;
#pragma unroll
    for (int dt = 0; dt < 8; dt++) {
        int d0 = dt * 8 + 2 * ct;
        float2 a;
        a.x = tf32_rna(O[dt][0] * li0);
        a.y = tf32_rna(O[dt][1] * li0);
        *(float2*)&out[(size_t)(b * NTOK + row0) * CDIM + h * HD + d0] = a;
        float2 c;
        c.x = tf32_rna(O[dt][2] * li1);
        c.y = tf32_rna(O[dt][3] * li1);
        *(float2*)&out[(size_t)(b * NTOK + row0 + 8) * CDIM + h * HD + d0] = c;
    }
}

// ============================================================================
// launch
// ============================================================================
extern "C" void kernel_launch(void* const* d_in, const int* in_sizes, int n_in,
                              void* d_out, int out_size)
{
    (void)in_sizes; (void)n_in; (void)out_size;
    const float* x      = (const float*)d_in[0];
    const float* w_qkv  = (const float*)d_in[1];
    const float* w_proj = (const float*)d_in[2];
    const float* b_proj = (const float*)d_in[3];
    float* out = (float*)d_out;

    float *q_p, *sc2_p, *ks_p, *vT_p, *ao_p, *xhi_p, *xlo_p;
    float *wqh_p, *wql_p, *wph_p, *wpl_p;
    int* keep_p;
    cudaGetSymbolAddress((void**)&q_p,    g_q);
    cudaGetSymbolAddress((void**)&sc2_p,  g_scores2);
    cudaGetSymbolAddress((void**)&keep_p, g_keep);
    cudaGetSymbolAddress((void**)&ks_p,   g_ksel);
    cudaGetSymbolAddress((void**)&vT_p,   g_vselT);
    cudaGetSymbolAddress((void**)&ao_p,   g_attnout);
    cudaGetSymbolAddress((void**)&xhi_p,  g_xhi);
    cudaGetSymbolAddress((void**)&xlo_p,  g_xlo);
    cudaGetSymbolAddress((void**)&wqh_p,  g_wqT_hi);
    cudaGetSymbolAddress((void**)&wql_p,  g_wqT_lo);
    cudaGetSymbolAddress((void**)&wph_p,  g_wpT_hi);
    cudaGetSymbolAddress((void**)&wpl_p,  g_wpT_lo);

    const int smem_q    = 3 * 8192 * (int)sizeof(float);   // 98304
    const int smem_proj = 3 * 8192 * (int)sizeof(float);   // 98304 (1-term CH32, 2 tiles)
    const int smem_kvg  = 3 * 8192 * (int)sizeof(float);   // 98304
    cudaFuncSetAttribute(q_gemm,    cudaFuncAttributeMaxDynamicSharedMemorySize, smem_q);
    cudaFuncSetAttribute(proj_gemm, cudaFuncAttributeMaxDynamicSharedMemorySize, smem_proj);
    cudaFuncSetAttribute(kvg_gemm,  cudaFuncAttributeMaxDynamicSharedMemorySize, smem_kvg);
    const int attn_smem = 3 * 8192 * (int)sizeof(float);   // 98304
    cudaFuncSetAttribute(attn_mma, cudaFuncAttributeMaxDynamicSharedMemorySize, attn_smem);

    // 0) prep: x split + both weight transpose/splits, one launch
    prep_kernel<<<XB + 96 * 24, 256>>>(x, xhi_p, xlo_p,
                                       w_qkv, wqh_p, wql_p, w_proj, wph_p, wpl_p);

    // 1) q = x @ w_q  (3-term tf32) + fused score partials
    q_gemm<<<dim3(CDIM / 128, ROWS / 128), 256, smem_q>>>(
        xhi_p, xlo_p, wqh_p, wql_p, q_p, sc2_p);

    // 2) top-k (bitonic set-selection)
    topk_kernel<<<NBH, 1024>>>(sc2_p, keep_p);

    // 3) gather-GEMM: Ksel / Vsel^T for selected tokens only
    kvg_gemm<<<dim3(KEEP / 128, NBH), 256, smem_kvg>>>(
        xhi_p, wqh_p, keep_p, ks_p, vT_p);

    // 4) attention on tensor cores (chunk 64, 2 CTAs/SM)
    attn_mma<<<dim3(NTOK / 128, NBH), 256, attn_smem>>>(q_p, ks_p, vT_p, ao_p);

    // 5) out = clip(attnout @ w_proj + b_proj, -10, 10)  (1-term tf32, CH32)
    proj_gemm<<<dim3(CDIM / 128, ROWS / 128), 256, smem_proj>>>(
        ao_p, wph_p, b_proj, out);
}